// round 14
// baseline (speedup 1.0000x reference)
#include <cuda_runtime.h>
#include <math.h>

#define NB   4096
#define LD   68
#define LDF  132

typedef unsigned long long ull;

__device__ __forceinline__ float2 unpack2(ull v) {
    float2 r; asm("mov.b64 {%0, %1}, %2;" : "=f"(r.x), "=f"(r.y) : "l"(v)); return r;
}
__device__ __forceinline__ ull pack2(float x, float y) {
    ull r; asm("mov.b64 %0, {%1, %2};" : "=l"(r) : "f"(x), "f"(y)); return r;
}
__device__ __forceinline__ ull ffma2(ull a, ull b, ull c) {
    ull r; asm("fma.rn.f32x2 %0, %1, %2, %3;" : "=l"(r) : "l"(a), "l"(b), "l"(c)); return r;
}
__device__ __forceinline__ ull mul2(ull a, ull b) {
    ull r; asm("mul.rn.f32x2 %0, %1, %2;" : "=l"(r) : "l"(a), "l"(b)); return r;
}
__device__ __forceinline__ float ex2f(float x) {
    float r; asm("ex2.approx.f32 %0, %1;" : "=f"(r) : "f"(x)); return r;
}
__device__ __forceinline__ float lg2f_(float x) {
    float r; asm("lg2.approx.f32 %0, %1;" : "=f"(r) : "f"(x)); return r;
}

#define LOG2E    1.4426950408889634f
#define LOG2_10  3.3219280948873623f
#define SGRP     (0.125f * LOG2E)
#define SATT     (0.25f  * LOG2E)

// ---------------- packed weights (all k-interleaved pairs unless noted) ----------------
#define CC_GRPM  0        // 2 x 4096  (M = Wq·Wk^T)
#define CC_U     8192     // 2 x 64    (u = Wq·bk)
#define CC_W     8320     // 2 x 64    (w = Wk·bq)
#define CC_K0    8448     // 2 (+pad)  (K0 = bq·bk)
#define CC_ZERO  8512     // 64 zeros
#define CC_AQ    8576     // 2 x 4096
#define CC_AK    16768    // 2 x 4096
#define CC_V     24960    // 2 x 4096
#define CC_O     33152    // 2 x 4096
#define CC_F1A   41344    // 2 x 4096  (ffn_w1 cols 0..63)
#define CC_F1B   49536    // 2 x 4096  (ffn_w1 cols 64..127)
#define CC_FFN2  57728    // 2 x 8192  (K=128)
#define WP_TOTAL 74112
__device__ float g_wpack[WP_TOTAL];

__global__ void pack_weights(const float* __restrict__ grp_wq,
                             const float* __restrict__ grp_wk,
                             const float* __restrict__ grp_bq,
                             const float* __restrict__ grp_bk,
                             const float* __restrict__ attn_w,
                             const float* __restrict__ ffn_w1,
                             const float* __restrict__ ffn_w2)
{
    int idx = blockIdx.x * 256 + threadIdx.x;
    if (idx >= WP_TOTAL) return;
    float v;
    if (idx < CC_U) {                        // M pairs: Mp[(kk*64+j)*2+s] = M[2kk+s][j]
        int off = idx;           int l = off >> 12; int r = off & 4095;
        int kk = r >> 7; int t = r & 127; int j = t >> 1; int s = t & 1;
        const float* wq = grp_wq + l*4096 + (2*kk + s)*64;
        const float* wk = grp_wk + l*4096 + j*64;
        float acc = 0.f;
        for (int d = 0; d < 64; d++) acc = fmaf(wq[d], wk[d], acc);
        v = acc;
    } else if (idx < CC_W) {                 // u[i] = Wq[i]·bk
        int off = idx - CC_U;    int l = off >> 6; int i = off & 63;
        const float* wq = grp_wq + l*4096 + i*64;
        const float* bk = grp_bk + l*64;
        float acc = 0.f;
        for (int d = 0; d < 64; d++) acc = fmaf(wq[d], bk[d], acc);
        v = acc;
    } else if (idx < CC_K0) {                // w[i] = Wk[i]·bq
        int off = idx - CC_W;    int l = off >> 6; int i = off & 63;
        const float* wk = grp_wk + l*4096 + i*64;
        const float* bq = grp_bq + l*64;
        float acc = 0.f;
        for (int d = 0; d < 64; d++) acc = fmaf(wk[d], bq[d], acc);
        v = acc;
    } else if (idx < CC_ZERO) {              // K0 (first 2 slots), rest zero
        int off = idx - CC_K0;
        if (off < 2) {
            const float* bq = grp_bq + off*64;
            const float* bk = grp_bk + off*64;
            float acc = 0.f;
            for (int d = 0; d < 64; d++) acc = fmaf(bq[d], bk[d], acc);
            v = acc;
        } else v = 0.f;
    } else if (idx < CC_AQ) {                // zero bias stub
        v = 0.f;
    } else if (idx < CC_AK) {                // attn Q pairs
        int off = idx - CC_AQ;   int l = off >> 12; int r = off & 4095;
        int kk = r >> 7; int t = r & 127; int j = t >> 1; int s = t & 1;
        v = attn_w[(l*4+0)*4096 + (2*kk+s)*64 + j];
    } else if (idx < CC_V) {                 // attn K pairs
        int off = idx - CC_AK;   int l = off >> 12; int r = off & 4095;
        int kk = r >> 7; int t = r & 127; int j = t >> 1; int s = t & 1;
        v = attn_w[(l*4+1)*4096 + (2*kk+s)*64 + j];
    } else if (idx < CC_O) {                 // V pairs
        int off = idx - CC_V;    int l = off >> 12; int r = off & 4095;
        int kk = r >> 7; int t = r & 127; int j = t >> 1; int s = t & 1;
        v = attn_w[(l*4+2)*4096 + (2*kk+s)*64 + j];
    } else if (idx < CC_F1A) {               // O pairs
        int off = idx - CC_O;    int l = off >> 12; int r = off & 4095;
        int kk = r >> 7; int t = r & 127; int j = t >> 1; int s = t & 1;
        v = attn_w[(l*4+3)*4096 + (2*kk+s)*64 + j];
    } else if (idx < CC_F1B) {               // ffn_w1 cols 0..63 pairs
        int off = idx - CC_F1A;  int l = off >> 12; int r = off & 4095;
        int kk = r >> 7; int t = r & 127; int j = t >> 1; int s = t & 1;
        v = ffn_w1[l*8192 + (2*kk+s)*128 + j];
    } else if (idx < CC_FFN2) {              // ffn_w1 cols 64..127 pairs
        int off = idx - CC_F1B;  int l = off >> 12; int r = off & 4095;
        int kk = r >> 7; int t = r & 127; int j = t >> 1; int s = t & 1;
        v = ffn_w1[l*8192 + (2*kk+s)*128 + 64 + j];
    } else {                                 // FFN2 pairs (K=128)
        int off = idx - CC_FFN2; int l = off >> 13; int r = off & 8191;
        int kk = r >> 7; int t = r & 127; int j = t >> 1; int s = t & 1;
        v = ffn_w2[l*8192 + (2*kk+s)*64 + j];
    }
    g_wpack[idx] = v;
}

struct Smem {
    float X [64*LD];
    float G [64*LD];
    float A [64*LD];
    float Bf[64*LD];
    float KV[2*64*LD];
    float m0[64], dv[64], isd[64];
    float s1[64], s2[64];
    float q1[64], q2[64], S[64];
    float rw[64], cum[64], pooled[64], pmL[64], pmR[64];
    int   tok[64];
    float scal[8];
};

// ---- single gemm on 4x2 warp grid with k-interleaved packed W (N=64)
template<int K, bool RELU, bool RES>
__device__ __forceinline__ void gemm2d_single(const float* __restrict__ Am, int lda,
                                              const float* __restrict__ Wp,
                                              const float* __restrict__ bias,
                                              float* __restrict__ Out, int ldo, int tid)
{
    const int warp = tid >> 5, lane = tid & 31;
    const int ly = lane >> 3, lx = lane & 7;
    const int wm = warp >> 1, wn = warp & 1;
    const int rbase = wm * 16 + ly;
    const int c0 = wn * 32 + lx * 4;
    ull acc[4][4];
    #pragma unroll
    for (int t = 0; t < 4; t++)
        #pragma unroll
        for (int c = 0; c < 4; c++) acc[t][c] = 0ull;

    #pragma unroll 4
    for (int kq = 0; kq < K/4; kq++) {
        ulonglong2 a[4];
        #pragma unroll
        for (int t = 0; t < 4; t++)
            a[t] = *(const ulonglong2*)(Am + (rbase + 4*t) * lda + 4*kq);
        const float* wb0 = Wp + ((2*kq    ) * 64 + c0) * 2;
        const float* wb1 = Wp + ((2*kq + 1) * 64 + c0) * 2;
        ulonglong2 w00 = *(const ulonglong2*)(wb0);
        ulonglong2 w01 = *(const ulonglong2*)(wb0 + 4);
        ulonglong2 w10 = *(const ulonglong2*)(wb1);
        ulonglong2 w11 = *(const ulonglong2*)(wb1 + 4);
        #pragma unroll
        for (int t = 0; t < 4; t++) {
            acc[t][0] = ffma2(a[t].x, w00.x, acc[t][0]);
            acc[t][1] = ffma2(a[t].x, w00.y, acc[t][1]);
            acc[t][2] = ffma2(a[t].x, w01.x, acc[t][2]);
            acc[t][3] = ffma2(a[t].x, w01.y, acc[t][3]);
            acc[t][0] = ffma2(a[t].y, w10.x, acc[t][0]);
            acc[t][1] = ffma2(a[t].y, w10.y, acc[t][1]);
            acc[t][2] = ffma2(a[t].y, w11.x, acc[t][2]);
            acc[t][3] = ffma2(a[t].y, w11.y, acc[t][3]);
        }
    }
    float4 bv = *(const float4*)(bias + c0);
    #pragma unroll
    for (int t = 0; t < 4; t++) {
        float2 p0 = unpack2(acc[t][0]);
        float2 p1 = unpack2(acc[t][1]);
        float2 p2 = unpack2(acc[t][2]);
        float2 p3 = unpack2(acc[t][3]);
        float4 st;
        st.x = p0.x + p0.y + bv.x;
        st.y = p1.x + p1.y + bv.y;
        st.z = p2.x + p2.y + bv.z;
        st.w = p3.x + p3.y + bv.w;
        if (RELU) {
            st.x = fmaxf(st.x, 0.f); st.y = fmaxf(st.y, 0.f);
            st.z = fmaxf(st.z, 0.f); st.w = fmaxf(st.w, 0.f);
        }
        float* op = Out + (rbase + 4*t) * ldo + c0;
        if (RES) {
            float4 old = *(float4*)op;
            st.x += old.x; st.y += old.y; st.z += old.z; st.w += old.w;
        }
        *(float4*)op = st;
    }
}

__device__ __forceinline__ void layernorm(const float* __restrict__ Xm,
                                          const float* __restrict__ g,
                                          const float* __restrict__ bb,
                                          float* __restrict__ Out, int tid)
{
    const int r = tid >> 2, c0 = (tid & 3) * 16;
    const float4* xr = (const float4*)(Xm + r * LD + c0);
    float4 v0 = xr[0], v1 = xr[1], v2 = xr[2], v3 = xr[3];
    float s = v0.x+v0.y+v0.z+v0.w + v1.x+v1.y+v1.z+v1.w
            + v2.x+v2.y+v2.z+v2.w + v3.x+v3.y+v3.z+v3.w;
    s += __shfl_xor_sync(0xffffffffu, s, 1);
    s += __shfl_xor_sync(0xffffffffu, s, 2);
    const float mu = s * (1.f / 64.f);
    float var = 0.f;
    {
        float d;
        d = v0.x - mu; var += d*d;  d = v0.y - mu; var += d*d;
        d = v0.z - mu; var += d*d;  d = v0.w - mu; var += d*d;
        d = v1.x - mu; var += d*d;  d = v1.y - mu; var += d*d;
        d = v1.z - mu; var += d*d;  d = v1.w - mu; var += d*d;
        d = v2.x - mu; var += d*d;  d = v2.y - mu; var += d*d;
        d = v2.z - mu; var += d*d;  d = v2.w - mu; var += d*d;
        d = v3.x - mu; var += d*d;  d = v3.y - mu; var += d*d;
        d = v3.z - mu; var += d*d;  d = v3.w - mu; var += d*d;
    }
    var += __shfl_xor_sync(0xffffffffu, var, 1);
    var += __shfl_xor_sync(0xffffffffu, var, 2);
    const float rstd = rsqrtf(var * (1.f / 64.f) + 1e-6f);
    const float4* gp = (const float4*)(g + c0);
    const float4* bp = (const float4*)(bb + c0);
    float4* op = (float4*)(Out + r * LD + c0);
    float4 xv, gv, bv4, ov;
    #pragma unroll
    for (int q = 0; q < 4; q++) {
        xv = (q==0)?v0:((q==1)?v1:((q==2)?v2:v3));
        gv = gp[q]; bv4 = bp[q];
        ov.x = gv.x * (xv.x - mu) * rstd + bv4.x;
        ov.y = gv.y * (xv.y - mu) * rstd + bv4.y;
        ov.z = gv.z * (xv.z - mu) * rstd + bv4.z;
        ov.w = gv.w * (xv.w - mu) * rstd + bv4.w;
        op[q] = ov;
    }
}

__global__ __launch_bounds__(256, 2) void fsa_kernel(
    const int*   __restrict__ tok_g,
    const float* __restrict__ emb,
    const float* __restrict__ np_w,   const float* __restrict__ np_b,
    const float* __restrict__ grp_ln_g, const float* __restrict__ grp_ln_b,
    const float* __restrict__ attn_b,
    const float* __restrict__ ln1_g,  const float* __restrict__ ln1_b,
    const float* __restrict__ ln2_g,  const float* __restrict__ ln2_b,
    const float* __restrict__ ffn_b1, const float* __restrict__ ffn_b2,
    const float* __restrict__ enc_g,  const float* __restrict__ enc_b,
    const float* __restrict__ red_w,  const float* __restrict__ red_b,
    const float* __restrict__ opc_w,  const float* __restrict__ opc_b,
    const float* __restrict__ res_w,  const float* __restrict__ res_b,
    float* __restrict__ out, int out_size)
{
    extern __shared__ float smraw[];
    Smem& sm = *reinterpret_cast<Smem*>(smraw);
    const int b   = blockIdx.x;
    const int tid = threadIdx.x;

    if (tid < 64) {
        int t = tok_g[b * 64 + tid];
        sm.tok[tid] = t;
        sm.m0[tid]  = (t != 0) ? 1.f : 0.f;
        float isd   = (t >= 4 && t <= 13) ? 1.f : 0.f;
        sm.isd[tid] = isd;
        sm.dv[tid]  = ((float)t - 4.f) * isd;
    }
    __syncthreads();

    unsigned mbit0, mbit1;
    {
        int lane = tid & 31;
        mbit0 = __ballot_sync(0xffffffffu, sm.m0[lane] > 0.f);
        mbit1 = __ballot_sync(0xffffffffu, sm.m0[lane + 32] > 0.f);
    }

    {
        const int r = tid >> 2, c0 = (tid & 3) * 16;
        const int t = sm.tok[r];
        const float isd  = sm.isd[r];
        const float dvv  = sm.dv[r];
        const float isop = (t >= 14 && t <= 17) ? 1.f : 0.f;
        const float opt  = isop * ((float)t - 13.f);
        const float* erow = emb + t * 64;
        const float kfreq2 = (float)(-13.287712379549449 / 64.0);
        #pragma unroll 4
        for (int c = 0; c < 16; c++) {
            int cc = c0 + c;
            float base = erow[cc] * 8.f
                       + dvv  * np_w[cc]       + isd  * np_w[64 + cc]
                       + opt  * np_w[128 + cc] + isop * np_w[192 + cc]
                       + np_b[cc];
            float freq = ex2f((float)(cc & ~1) * kfreq2);
            float ang  = (float)r * freq;
            float pe   = (cc & 1) ? __cosf(ang) : __sinf(ang);
            sm.X[r * LD + cc] = base + pe;
        }
    }
    __syncthreads();

    float* const Kb = sm.KV;
    float* const Vb = sm.KV + 64 * LD;

    #pragma unroll 1
    for (int l = 0; l < 2; l++) {
        // ---- group attention -> G ----
        layernorm(sm.X, grp_ln_g + l * 64, grp_ln_b + l * 64, sm.A, tid);
        __syncthreads();
        gemm2d_single<64,false,false>(sm.A, LD, g_wpack + CC_GRPM + l*4096,
                                      g_wpack + CC_ZERO, sm.Bf, LD, tid);
        if (tid < 64) {   // pu = c_i·u , pw = c_i·w
            const ulonglong2* cr = (const ulonglong2*)(sm.A + tid * LD);
            const ulonglong2* up = (const ulonglong2*)(g_wpack + CC_U + l*64);
            const ulonglong2* wp = (const ulonglong2*)(g_wpack + CC_W + l*64);
            ull au = 0ull, aw = 0ull;
            #pragma unroll 4
            for (int m = 0; m < 16; m++) {
                ulonglong2 c = cr[m], uu = up[m], ww = wp[m];
                au = ffma2(c.x, uu.x, au); au = ffma2(c.y, uu.y, au);
                aw = ffma2(c.x, ww.x, aw); aw = ffma2(c.y, ww.y, aw);
            }
            float2 pu = unpack2(au), pw = unpack2(aw);
            sm.pmL[tid] = pu.x + pu.y;
            sm.pmR[tid] = pw.x + pw.y;
        }
        __syncthreads();
        if (tid < 63 || (tid >= 64 && tid < 127)) {
            const int up = (tid < 63);
            const int i  = up ? tid : (tid - 64);
            const ulonglong2* zp = (const ulonglong2*)(sm.Bf + (up ? i : i + 1) * LD);
            const ulonglong2* cp = (const ulonglong2*)(sm.A  + (up ? i + 1 : i) * LD);
            ull acc = 0ull;
            #pragma unroll 4
            for (int m = 0; m < 16; m++) {
                ulonglong2 z4 = zp[m], c4 = cp[m];
                acc = ffma2(z4.x, c4.x, acc);
                acc = ffma2(z4.y, c4.y, acc);
            }
            float2 p = unpack2(acc);
            float extra = up ? (sm.pmL[i] + sm.pmR[i + 1])
                             : (sm.pmL[i + 1] + sm.pmR[i]);
            float sv = (p.x + p.y + extra + g_wpack[CC_K0 + l]) * SGRP;
            if (up) sm.s1[i] = sv; else sm.s2[i] = sv;
        }
        __syncthreads();
        if (tid < 64) {
            const int i = tid;
            const float m_i = sm.m0[i];
            bool vL = (i > 0)  && m_i > 0.f && sm.m0[i-1] > 0.f;
            bool vR = (i < 63) && m_i > 0.f && sm.m0[i+1] > 0.f;
            float pr_i, ps_i;
            if (!vL && !vR) { pr_i = 1.f/64.f; ps_i = 1.f/64.f; }
            else {
                float sL = vL ? sm.s2[i-1] : -3.4e38f;
                float sR = vR ? sm.s1[i]   : -3.4e38f;
                float m  = fmaxf(sL, sR);
                float eL = vL ? ex2f(sL - m) : 0.f;
                float eR = vR ? ex2f(sR - m) : 0.f;
                pr_i = eR / (eL + eR); ps_i = 0.f;
            }
            float nbd = sqrtf(ps_i * ps_i + 1e-9f);
            if (l > 0) { float pp = sm.G[i * LD + i]; nbd = pp + (1.f - pp) * nbd; }
            sm.q1[i] = nbd;
            if (i < 63) {
                const int i1 = i + 1;
                bool vL1 = m_i > 0.f && sm.m0[i1] > 0.f;
                bool vR1 = (i1 < 63) && sm.m0[i1] > 0.f && sm.m0[i1+1] > 0.f;
                float pl1;
                if (!vL1 && !vR1) pl1 = 1.f/64.f;
                else {
                    float sL = vL1 ? sm.s2[i]  : -3.4e38f;
                    float sR = vR1 ? sm.s1[i1] : -3.4e38f;
                    float m  = fmaxf(sL, sR);
                    float eL = vL1 ? ex2f(sL - m) : 0.f;
                    float eR = vR1 ? ex2f(sR - m) : 0.f;
                    pl1 = eL / (eL + eR);
                }
                float nbu = sqrtf(pr_i * pl1 + 1e-9f);
                if (l > 0) { float pp = sm.G[i * LD + i1]; nbu = pp + (1.f - pp) * nbu; }
                sm.q2[i] = lg2f_(nbu + 1e-9f);
            } else {
                sm.q2[63] = 0.f;
            }
        }
        __syncthreads();
        if (tid < 32) {   // exclusive scan of q2 -> S
            float a0 = sm.q2[2*tid], a1 = sm.q2[2*tid+1];
            float p = a0 + a1;
            #pragma unroll
            for (int d = 1; d < 32; d <<= 1) {
                float tshf = __shfl_up_sync(0xffffffffu, p, d);
                if ((int)tid >= d) p += tshf;
            }
            sm.S[2*tid+1] = p - a1;
            if (tid < 31) sm.S[2*tid+2] = p;
            if (tid == 0) sm.S[0] = 0.f;
        }
        __syncthreads();
        for (int t = tid; t < 4096; t += 256) {
            int i = t >> 6, j = t & 63;
            float v;
            if (i == j) v = sm.q1[i];
            else {
                int lo = (i < j) ? i : j, hi2 = (i < j) ? j : i;
                v = ex2f(sm.S[hi2] - sm.S[lo]) + 1e-9f;
            }
            sm.G[i * LD + j] = v;
        }
        __syncthreads();

        // ---- multi-head attention ----
        layernorm(sm.X, ln1_g + l * 64, ln1_b + l * 64, sm.A, tid);
        __syncthreads();
        gemm2d_single<64,false,false>(sm.A, LD, g_wpack + CC_AQ + l*4096,
                                      attn_b + (l*4+0)*64, sm.Bf, LD, tid);
        gemm2d_single<64,false,false>(sm.A, LD, g_wpack + CC_AK + l*4096,
                                      attn_b + (l*4+1)*64, Kb, LD, tid);
        gemm2d_single<64,false,false>(sm.A, LD, g_wpack + CC_V + l*4096,
                                      attn_b + (l*4+2)*64, Vb, LD, tid);
        __syncthreads();
        // fused attention: thread = (head, row); unnormalized softmax single pass
        {
            const int warp = tid >> 5, lane = tid & 31;
            const int h = warp >> 1;
            const int r = (warp & 1) * 32 + lane;
            const ull satt2 = pack2(SATT, SATT);
            const ulonglong2* qp = (const ulonglong2*)(sm.Bf + r * LD + h * 16);
            ulonglong2 qA = qp[0], qB = qp[1], qC = qp[2], qD = qp[3];
            qA.x = mul2(qA.x, satt2); qA.y = mul2(qA.y, satt2);
            qB.x = mul2(qB.x, satt2); qB.y = mul2(qB.y, satt2);
            qC.x = mul2(qC.x, satt2); qC.y = mul2(qC.y, satt2);
            qD.x = mul2(qD.x, satt2); qD.y = mul2(qD.y, satt2);
            ull o[8];
            #pragma unroll
            for (int k = 0; k < 8; k++) o[k] = 0ull;
            float Z = 0.f;
            #pragma unroll 4
            for (int j = 0; j < 64; j++) {
                const ulonglong2* kp = (const ulonglong2*)(Kb + j * LD + h * 16);
                ulonglong2 kA = kp[0], kB = kp[1], kC = kp[2], kD = kp[3];
                ull acc = 0ull;
                acc = ffma2(qA.x, kA.x, acc);
                acc = ffma2(qA.y, kA.y, acc);
                acc = ffma2(qB.x, kB.x, acc);
                acc = ffma2(qB.y, kB.y, acc);
                acc = ffma2(qC.x, kC.x, acc);
                acc = ffma2(qC.y, kC.y, acc);
                acc = ffma2(qD.x, kD.x, acc);
                acc = ffma2(qD.y, kD.y, acc);
                float2 p = unpack2(acc);
                unsigned vbit = (j < 32) ? (mbit0 >> j) : (mbit1 >> (j - 32));
                float e = (vbit & 1u) ? ex2f(p.x + p.y) : 0.f;
                Z += e;
                float w = e * sm.G[j * LD + r];
                ull wb = pack2(w, w);
                const ulonglong2* vp = (const ulonglong2*)(Vb + j * LD + h * 16);
                ulonglong2 vA = vp[0], vB = vp[1], vC = vp[2], vD = vp[3];
                o[0] = ffma2(wb, vA.x, o[0]); o[1] = ffma2(wb, vA.y, o[1]);
                o[2] = ffma2(wb, vB.x, o[2]); o[3] = ffma2(wb, vB.y, o[3]);
                o[4] = ffma2(wb, vC.x, o[4]); o[5] = ffma2(wb, vC.y, o[5]);
                o[6] = ffma2(wb, vD.x, o[6]); o[7] = ffma2(wb, vD.y, o[7]);
            }
            if (Z == 0.f) {   // all-masked row: reference softmax uniform 1/64
                #pragma unroll
                for (int k = 0; k < 8; k++) o[k] = 0ull;
                for (int j = 0; j < 64; j++) {
                    float w = sm.G[j * LD + r] * 0.015625f;
                    ull wb = pack2(w, w);
                    const ulonglong2* vp = (const ulonglong2*)(Vb + j * LD + h * 16);
                    ulonglong2 vA = vp[0], vB = vp[1], vC = vp[2], vD = vp[3];
                    o[0] = ffma2(wb, vA.x, o[0]); o[1] = ffma2(wb, vA.y, o[1]);
                    o[2] = ffma2(wb, vB.x, o[2]); o[3] = ffma2(wb, vB.y, o[3]);
                    o[4] = ffma2(wb, vC.x, o[4]); o[5] = ffma2(wb, vC.y, o[5]);
                    o[6] = ffma2(wb, vD.x, o[6]); o[7] = ffma2(wb, vD.y, o[7]);
                }
                Z = 1.f;
            }
            const float invZ = 1.f / Z;
            const ull zb = pack2(invZ, invZ);
            float* op = sm.Bf + r * LD + h * 16;
            #pragma unroll
            for (int k = 0; k < 4; k++) {
                float2 pa = unpack2(mul2(o[2*k],   zb));
                float2 pb = unpack2(mul2(o[2*k+1], zb));
                float4 st; st.x = pa.x; st.y = pa.y; st.z = pb.x; st.w = pb.y;
                *(float4*)(op + 4*k) = st;
            }
        }
        __syncthreads();
        gemm2d_single<64,false,true>(sm.Bf, LD, g_wpack + CC_O + l*4096,
                                     attn_b + (l*4+3)*64, sm.X, LD, tid);
        __syncthreads();

        // ---- FFN ----
        layernorm(sm.X, ln2_g + l * 64, ln2_b + l * 64, sm.A, tid);
        __syncthreads();
        gemm2d_single<64,true,false>(sm.A, LD, g_wpack + CC_F1A + l*4096,
                                     ffn_b1 + l*128,      sm.KV,      LDF, tid);
        gemm2d_single<64,true,false>(sm.A, LD, g_wpack + CC_F1B + l*4096,
                                     ffn_b1 + l*128 + 64, sm.KV + 64, LDF, tid);
        __syncthreads();
        gemm2d_single<128,false,true>(sm.KV, LDF, g_wpack + CC_FFN2 + l*8192,
                                      ffn_b2 + l*64, sm.X, LD, tid);
        __syncthreads();
    }

    // ================= readout =================
    layernorm(sm.X, enc_g, enc_b, sm.A, tid);
    __syncthreads();
    if (tid < 64) {
        const ulonglong2* xr = (const ulonglong2*)(sm.A + tid * LD);
        const ulonglong2* wr = (const ulonglong2*)red_w;
        ull acc = 0ull;
        #pragma unroll 4
        for (int m = 0; m < 16; m++) {
            ulonglong2 x4 = xr[m], w4 = wr[m];
            acc = ffma2(x4.x, w4.x, acc);
            acc = ffma2(x4.y, w4.y, acc);
        }
        float2 p = unpack2(acc);
        float s = p.x + p.y + red_b[0];
        s += (1.f - sm.m0[tid]) * (-1e9f);
        sm.s1[tid] = s;
    }
    __syncthreads();
    if (tid < 32) {
        float m = fmaxf(sm.s1[tid], sm.s1[tid + 32]);
        #pragma unroll
        for (int d = 16; d >= 1; d >>= 1) m = fmaxf(m, __shfl_xor_sync(0xffffffffu, m, d));
        if (tid == 0) sm.scal[0] = m;
    }
    __syncthreads();
    if (tid < 64) sm.s2[tid] = ex2f((sm.s1[tid] - sm.scal[0]) * LOG2E);
    __syncthreads();
    if (tid < 32) {
        float z = sm.s2[tid] + sm.s2[tid + 32];
        #pragma unroll
        for (int d = 16; d >= 1; d >>= 1) z += __shfl_xor_sync(0xffffffffu, z, d);
        if (tid == 0) sm.scal[1] = z;
    }
    __syncthreads();
    if (tid < 64) sm.rw[tid] = sm.s2[tid] / sm.scal[1];
    __syncthreads();
    if (tid < 32) {
        float a0 = sm.rw[2*tid], a1 = sm.rw[2*tid+1];
        float p = a0 + a1;
        #pragma unroll
        for (int d = 1; d < 32; d <<= 1) {
            float tshf = __shfl_up_sync(0xffffffffu, p, d);
            if ((int)tid >= d) p += tshf;
        }
        sm.cum[2*tid+1] = p;
        sm.cum[2*tid]   = p - a1;
    }
    __syncthreads();
    if (tid < 64) {
        sm.pmL[tid] = (1.f - sm.cum[tid]) * sm.isd[tid];
        sm.pmR[tid] = (sm.cum[tid] - sm.rw[tid]) * sm.isd[tid];
    }
    if (tid >= 64 && tid < 128) {
        int h = tid - 64;
        float p = 0.f;
        #pragma unroll 8
        for (int ll = 0; ll < 64; ll++) p = fmaf(sm.A[ll * LD + h], sm.rw[ll], p);
        sm.pooled[h] = p;
    }
    __syncthreads();
    if (tid < 64) {
        const int lane = tid & 31;
        const float* pm = (tid < 32) ? sm.pmL : sm.pmR;
        float a0 = pm[2*lane], a1 = pm[2*lane+1];
        float p = a0 + a1;
        #pragma unroll
        for (int d = 1; d < 32; d <<= 1) {
            float tshf = __shfl_up_sync(0xffffffffu, p, d);
            if (lane >= d) p += tshf;
        }
        float tot  = __shfl_sync(0xffffffffu, p, 31);
        float run1 = p, run0 = p - a1;
        float d0 = sm.dv[2*lane], d1 = sm.dv[2*lane+1];
        float acc = d0 * ex2f((tot - run0) * a0 * LOG2_10) * a0
                  + d1 * ex2f((tot - run1) * a1 * LOG2_10) * a1;
        #pragma unroll
        for (int d = 16; d >= 1; d >>= 1) acc += __shfl_xor_sync(0xffffffffu, acc, d);
        if (lane == 0) sm.scal[(tid < 32) ? 5 : 6] = acc;
    } else if (tid >= 64 && tid < 96) {
        const int lane = tid & 31;
        float p0 = sm.pooled[lane], p1 = sm.pooled[lane + 32];
        float l0 = p0 * opc_w[lane*4+0] + p1 * opc_w[(lane+32)*4+0];
        float l1 = p0 * opc_w[lane*4+1] + p1 * opc_w[(lane+32)*4+1];
        float l2 = p0 * opc_w[lane*4+2] + p1 * opc_w[(lane+32)*4+2];
        float l3 = p0 * opc_w[lane*4+3] + p1 * opc_w[(lane+32)*4+3];
        #pragma unroll
        for (int d = 16; d >= 1; d >>= 1) {
            l0 += __shfl_xor_sync(0xffffffffu, l0, d);
            l1 += __shfl_xor_sync(0xffffffffu, l1, d);
            l2 += __shfl_xor_sync(0xffffffffu, l2, d);
            l3 += __shfl_xor_sync(0xffffffffu, l3, d);
        }
        if (lane == 0) {
            sm.s1[0] = l0 + opc_b[0];
            sm.s1[1] = l1 + opc_b[1];
            sm.s1[2] = l2 + opc_b[2];
            sm.s1[3] = l3 + opc_b[3];
        }
    }
    __syncthreads();
    if (tid == 0) {
        float lv = sm.scal[5], rv = sm.scal[6];
        float lg0 = sm.s1[0], lg1 = sm.s1[1], lg2 = sm.s1[2], lg3 = sm.s1[3];
        int op = 0; float bm = lg0;
        if (lg1 > bm) { bm = lg1; op = 1; }
        if (lg2 > bm) { bm = lg2; op = 2; }
        if (lg3 > bm) { bm = lg3; op = 3; }
        float result, valid = 1.f;
        if      (op == 0) result = lv + rv;
        else if (op == 1) result = lv - rv;
        else if (op == 2) result = lv * rv;
        else {
            bool bad = fabsf(rv) < 1e-6f;
            result = bad ? 0.f : lv / rv;
            valid  = bad ? 0.f : 1.f;
        }
        float sgn = (result > 0.f) ? 1.f : ((result < 0.f) ? -1.f : 0.f);
        float rc  = sgn * log1pf(fabsf(result));
        sm.scal[2] = result; sm.scal[3] = valid; sm.scal[4] = rc;
    }
    __syncthreads();

    const bool full = (out_size >= 136 * NB);
    if (full) {
        if (tid == 0) {
            out[b]           = sm.scal[2];
            out[65*NB + b]   = sm.scal[3];
            out[66*NB + b]   = sm.scal[5];
            out[67*NB + b]   = sm.scal[6];
            #pragma unroll
            for (int o = 0; o < 4; o++) out[68*NB + b*4 + o] = sm.s1[o];
        }
        if (tid < 64) {
            float rc = sm.scal[4], valid = sm.scal[3];
            out[NB + b*64 + tid]    = rc * res_w[tid] + valid * res_w[64 + tid] + res_b[tid];
            out[72*NB + b*64 + tid] = sm.rw[tid];
        }
    } else {
        if (tid == 0) out[b] = sm.scal[2];
    }
}

extern "C" void kernel_launch(void* const* d_in, const int* in_sizes, int n_in,
                              void* d_out, int out_size)
{
    pack_weights<<<(WP_TOTAL + 255) / 256, 256>>>(
        (const float*)d_in[4],   // grp_wq
        (const float*)d_in[6],   // grp_wk
        (const float*)d_in[5],   // grp_bq
        (const float*)d_in[7],   // grp_bk
        (const float*)d_in[10],  // attn_w
        (const float*)d_in[16],  // ffn_w1
        (const float*)d_in[18]); // ffn_w2

    const size_t shmem = sizeof(Smem);
    cudaFuncSetAttribute(fsa_kernel, cudaFuncAttributeMaxDynamicSharedMemorySize, (int)shmem);
    fsa_kernel<<<NB, 256, shmem>>>(
        (const int*)  d_in[0],
        (const float*)d_in[1],
        (const float*)d_in[2],  (const float*)d_in[3],    // np_w, np_b
        (const float*)d_in[8],  (const float*)d_in[9],    // grp_ln_g, grp_ln_b
        (const float*)d_in[11],                            // attn_b
        (const float*)d_in[12], (const float*)d_in[13],   // ln1_g, ln1_b
        (const float*)d_in[14], (const float*)d_in[15],   // ln2_g, ln2_b
        (const float*)d_in[17], (const float*)d_in[19],   // ffn_b1, ffn_b2
        (const float*)d_in[20], (const float*)d_in[21],   // enc_g, enc_b
        (const float*)d_in[22], (const float*)d_in[23],   // red_w, red_b
        (const float*)d_in[24], (const float*)d_in[25],   // opc_w, opc_b
        (const float*)d_in[26], (const float*)d_in[27],   // res_w, res_b
        (float*)d_out, out_size);
}

// round 15
// speedup vs baseline: 1.1237x; 1.1237x over previous
#include <cuda_runtime.h>
#include <math.h>

#define NB   4096
#define LD   68
#define LDF  132

typedef unsigned long long ull;

__device__ __forceinline__ float2 unpack2(ull v) {
    float2 r; asm("mov.b64 {%0, %1}, %2;" : "=f"(r.x), "=f"(r.y) : "l"(v)); return r;
}
__device__ __forceinline__ ull pack2(float x, float y) {
    ull r; asm("mov.b64 %0, {%1, %2};" : "=l"(r) : "f"(x), "f"(y)); return r;
}
__device__ __forceinline__ ull ffma2(ull a, ull b, ull c) {
    ull r; asm("fma.rn.f32x2 %0, %1, %2, %3;" : "=l"(r) : "l"(a), "l"(b), "l"(c)); return r;
}
__device__ __forceinline__ ull mul2(ull a, ull b) {
    ull r; asm("mul.rn.f32x2 %0, %1, %2;" : "=l"(r) : "l"(a), "l"(b)); return r;
}
__device__ __forceinline__ float ex2f(float x) {
    float r; asm("ex2.approx.f32 %0, %1;" : "=f"(r) : "f"(x)); return r;
}
__device__ __forceinline__ float lg2f_(float x) {
    float r; asm("lg2.approx.f32 %0, %1;" : "=f"(r) : "f"(x)); return r;
}

#define LOG2E    1.4426950408889634f
#define LOG2_10  3.3219280948873623f
#define SGRP     (0.125f * LOG2E)
#define SATT     (0.25f  * LOG2E)

// ---------------- packed weights ----------------
// CC_GRPM: M = Wq·Wk^T per layer, k-interleaved pairs (N=64)
// CC_U/CC_W/CC_K0: u=Wq·bk, w=Wk·bq, K0=bq·bk ; CC_ZERO: 64 zeros (bias stub)
// CC_AQK: attn Q|K concat [k][128] ; CC_V/CC_O/CC_FFN2: k-interleaved pairs
#define CC_GRPM  0        // 2 x 4096
#define CC_U     8192     // 2 x 64
#define CC_W     8320     // 2 x 64
#define CC_K0    8448     // 2 (+pad to 64)
#define CC_ZERO  8512     // 64 zeros
#define CC_AQK   8576     // 2 x 8192
#define CC_V     24960    // 2 x 4096
#define CC_O     33152    // 2 x 4096
#define CC_FFN2  41344    // 2 x 8192
#define WP_TOTAL 57728
__device__ float g_wpack[WP_TOTAL];

__global__ void pack_weights(const float* __restrict__ grp_wq,
                             const float* __restrict__ grp_wk,
                             const float* __restrict__ grp_bq,
                             const float* __restrict__ grp_bk,
                             const float* __restrict__ attn_w,
                             const float* __restrict__ ffn_w2)
{
    int idx = blockIdx.x * 256 + threadIdx.x;
    if (idx >= WP_TOTAL) return;
    float v;
    if (idx < CC_U) {                        // M pairs: Mp[(kk*64+j)*2+s] = M[2kk+s][j]
        int off = idx;           int l = off >> 12; int r = off & 4095;
        int kk = r >> 7; int t = r & 127; int j = t >> 1; int s = t & 1;
        int a = 2*kk + s;
        const float* wq = grp_wq + l*4096 + a*64;
        const float* wk = grp_wk + l*4096 + j*64;
        float acc = 0.f;
        for (int d = 0; d < 64; d++) acc = fmaf(wq[d], wk[d], acc);
        v = acc;
    } else if (idx < CC_W) {                 // u[i] = Wq[i]·bk
        int off = idx - CC_U;    int l = off >> 6; int i = off & 63;
        const float* wq = grp_wq + l*4096 + i*64;
        const float* bk = grp_bk + l*64;
        float acc = 0.f;
        for (int d = 0; d < 64; d++) acc = fmaf(wq[d], bk[d], acc);
        v = acc;
    } else if (idx < CC_K0) {                // w[i] = Wk[i]·bq
        int off = idx - CC_W;    int l = off >> 6; int i = off & 63;
        const float* wk = grp_wk + l*4096 + i*64;
        const float* bq = grp_bq + l*64;
        float acc = 0.f;
        for (int d = 0; d < 64; d++) acc = fmaf(wk[d], bq[d], acc);
        v = acc;
    } else if (idx < CC_ZERO) {              // K0 (first 2 slots), rest zero
        int off = idx - CC_K0;
        if (off < 2) {
            const float* bq = grp_bq + off*64;
            const float* bk = grp_bk + off*64;
            float acc = 0.f;
            for (int d = 0; d < 64; d++) acc = fmaf(bq[d], bk[d], acc);
            v = acc;
        } else v = 0.f;
    } else if (idx < CC_AQK) {               // zero bias region
        v = 0.f;
    } else if (idx < CC_V) {                 // attn Q|K concat
        int off = idx - CC_AQK;  int l = off >> 13; int r = off & 8191;
        int k = r >> 7; int c = r & 127;
        v = attn_w[(l*4 + (c>>6))*4096 + k*64 + (c&63)];
    } else if (idx < CC_O) {                 // V pairs
        int off = idx - CC_V;    int l = off >> 12; int r = off & 4095;
        int kk = r >> 7; int t = r & 127; int j = t >> 1; int s = t & 1;
        v = attn_w[(l*4+2)*4096 + (2*kk+s)*64 + j];
    } else if (idx < CC_FFN2) {              // O pairs
        int off = idx - CC_O;    int l = off >> 12; int r = off & 4095;
        int kk = r >> 7; int t = r & 127; int j = t >> 1; int s = t & 1;
        v = attn_w[(l*4+3)*4096 + (2*kk+s)*64 + j];
    } else {                                 // FFN2 pairs (K=128)
        int off = idx - CC_FFN2; int l = off >> 13; int r = off & 8191;
        int kk = r >> 7; int t = r & 127; int j = t >> 1; int s = t & 1;
        v = ffn_w2[l*8192 + (2*kk+s)*64 + j];
    }
    g_wpack[idx] = v;
}

struct Smem {
    float X [64*LD];
    float G [64*LD];
    float A [64*LD];
    float Bf[64*LD];
    float KV[2*64*LD];
    float m0[64], dv[64], isd[64];
    float s1[64], s2[64];
    float q1[64], q2[64], S[64];
    float rw[64], cum[64], pooled[64], pmL[64], pmR[64];
    int   tok[64];
    float scal[8];
};

// ---- dual gemm on 2x4 warp grid: A(64x64) @ W[64][128] -> Out0|Out1
#define DROW(t, av) \
    acc[t][0] = fmaf(av, w.x, acc[t][0]); \
    acc[t][1] = fmaf(av, w.y, acc[t][1]); \
    acc[t][2] = fmaf(av, w.z, acc[t][2]); \
    acc[t][3] = fmaf(av, w.w, acc[t][3]);

#define DALL(comp) \
    DROW(0, a[0].comp) DROW(1, a[1].comp) DROW(2, a[2].comp) DROW(3, a[3].comp) \
    DROW(4, a[4].comp) DROW(5, a[5].comp) DROW(6, a[6].comp) DROW(7, a[7].comp)

template<bool RELU>
__device__ __forceinline__ void gemm2d_dual(const float* __restrict__ Am, int lda,
                                            const float* __restrict__ W,   // ldw=128
                                            const float* __restrict__ bias0,
                                            const float* __restrict__ bias1,
                                            float* __restrict__ Out0,
                                            float* __restrict__ Out1,
                                            int ldo, int tid)
{
    const int warp = tid >> 5, lane = tid & 31;
    const int ly = lane >> 3, lx = lane & 7;
    const int wm = warp >> 2, wn = warp & 3;
    const int rbase = wm * 32 + ly;
    const int c0 = wn * 32 + lx * 4;
    float acc[8][4];
    #pragma unroll
    for (int t = 0; t < 8; t++)
        #pragma unroll
        for (int c = 0; c < 4; c++) acc[t][c] = 0.f;

    #pragma unroll 2
    for (int kq = 0; kq < 16; kq++) {
        float4 a[8];
        #pragma unroll
        for (int t = 0; t < 8; t++)
            a[t] = *(const float4*)(Am + (rbase + 4*t) * lda + 4*kq);
        { float4 w = *(const float4*)(W + (4*kq + 0) * 128 + c0); DALL(x) }
        { float4 w = *(const float4*)(W + (4*kq + 1) * 128 + c0); DALL(y) }
        { float4 w = *(const float4*)(W + (4*kq + 2) * 128 + c0); DALL(z) }
        { float4 w = *(const float4*)(W + (4*kq + 3) * 128 + c0); DALL(w) }
    }
    const float* bp = (c0 < 64) ? (bias0 + c0) : (bias1 + c0 - 64);
    float* ob       = (c0 < 64) ? (Out0 + c0)  : (Out1 + c0 - 64);
    float4 bv = *(const float4*)bp;
    #pragma unroll
    for (int t = 0; t < 8; t++) {
        float4 st;
        st.x = acc[t][0] + bv.x; st.y = acc[t][1] + bv.y;
        st.z = acc[t][2] + bv.z; st.w = acc[t][3] + bv.w;
        if (RELU) {
            st.x = fmaxf(st.x, 0.f); st.y = fmaxf(st.y, 0.f);
            st.z = fmaxf(st.z, 0.f); st.w = fmaxf(st.w, 0.f);
        }
        *(float4*)(ob + (rbase + 4*t) * ldo) = st;
    }
}

// ---- single gemm on 4x2 warp grid with k-interleaved packed W
template<int K, bool RELU, bool RES>
__device__ __forceinline__ void gemm2d_single(const float* __restrict__ Am, int lda,
                                              const float* __restrict__ Wp,
                                              const float* __restrict__ bias,
                                              float* __restrict__ Out, int ldo, int tid)
{
    const int warp = tid >> 5, lane = tid & 31;
    const int ly = lane >> 3, lx = lane & 7;
    const int wm = warp >> 1, wn = warp & 1;
    const int rbase = wm * 16 + ly;
    const int c0 = wn * 32 + lx * 4;
    ull acc[4][4];
    #pragma unroll
    for (int t = 0; t < 4; t++)
        #pragma unroll
        for (int c = 0; c < 4; c++) acc[t][c] = 0ull;

    #pragma unroll 4
    for (int kq = 0; kq < K/4; kq++) {
        ulonglong2 a[4];
        #pragma unroll
        for (int t = 0; t < 4; t++)
            a[t] = *(const ulonglong2*)(Am + (rbase + 4*t) * lda + 4*kq);
        const float* wb0 = Wp + ((2*kq    ) * 64 + c0) * 2;
        const float* wb1 = Wp + ((2*kq + 1) * 64 + c0) * 2;
        ulonglong2 w00 = *(const ulonglong2*)(wb0);
        ulonglong2 w01 = *(const ulonglong2*)(wb0 + 4);
        ulonglong2 w10 = *(const ulonglong2*)(wb1);
        ulonglong2 w11 = *(const ulonglong2*)(wb1 + 4);
        #pragma unroll
        for (int t = 0; t < 4; t++) {
            acc[t][0] = ffma2(a[t].x, w00.x, acc[t][0]);
            acc[t][1] = ffma2(a[t].x, w00.y, acc[t][1]);
            acc[t][2] = ffma2(a[t].x, w01.x, acc[t][2]);
            acc[t][3] = ffma2(a[t].x, w01.y, acc[t][3]);
            acc[t][0] = ffma2(a[t].y, w10.x, acc[t][0]);
            acc[t][1] = ffma2(a[t].y, w10.y, acc[t][1]);
            acc[t][2] = ffma2(a[t].y, w11.x, acc[t][2]);
            acc[t][3] = ffma2(a[t].y, w11.y, acc[t][3]);
        }
    }
    float4 bv = *(const float4*)(bias + c0);
    #pragma unroll
    for (int t = 0; t < 4; t++) {
        float2 p0 = unpack2(acc[t][0]);
        float2 p1 = unpack2(acc[t][1]);
        float2 p2 = unpack2(acc[t][2]);
        float2 p3 = unpack2(acc[t][3]);
        float4 st;
        st.x = p0.x + p0.y + bv.x;
        st.y = p1.x + p1.y + bv.y;
        st.z = p2.x + p2.y + bv.z;
        st.w = p3.x + p3.y + bv.w;
        if (RELU) {
            st.x = fmaxf(st.x, 0.f); st.y = fmaxf(st.y, 0.f);
            st.z = fmaxf(st.z, 0.f); st.w = fmaxf(st.w, 0.f);
        }
        float* op = Out + (rbase + 4*t) * ldo + c0;
        if (RES) {
            float4 old = *(float4*)op;
            st.x += old.x; st.y += old.y; st.z += old.z; st.w += old.w;
        }
        *(float4*)op = st;
    }
}

__device__ __forceinline__ void layernorm(const float* __restrict__ Xm,
                                          const float* __restrict__ g,
                                          const float* __restrict__ bb,
                                          float* __restrict__ Out, int tid)
{
    const int r = tid >> 2, c0 = (tid & 3) * 16;
    const float4* xr = (const float4*)(Xm + r * LD + c0);
    float4 v0 = xr[0], v1 = xr[1], v2 = xr[2], v3 = xr[3];
    float s = v0.x+v0.y+v0.z+v0.w + v1.x+v1.y+v1.z+v1.w
            + v2.x+v2.y+v2.z+v2.w + v3.x+v3.y+v3.z+v3.w;
    s += __shfl_xor_sync(0xffffffffu, s, 1);
    s += __shfl_xor_sync(0xffffffffu, s, 2);
    const float mu = s * (1.f / 64.f);
    float var = 0.f;
    {
        float d;
        d = v0.x - mu; var += d*d;  d = v0.y - mu; var += d*d;
        d = v0.z - mu; var += d*d;  d = v0.w - mu; var += d*d;
        d = v1.x - mu; var += d*d;  d = v1.y - mu; var += d*d;
        d = v1.z - mu; var += d*d;  d = v1.w - mu; var += d*d;
        d = v2.x - mu; var += d*d;  d = v2.y - mu; var += d*d;
        d = v2.z - mu; var += d*d;  d = v2.w - mu; var += d*d;
        d = v3.x - mu; var += d*d;  d = v3.y - mu; var += d*d;
        d = v3.z - mu; var += d*d;  d = v3.w - mu; var += d*d;
    }
    var += __shfl_xor_sync(0xffffffffu, var, 1);
    var += __shfl_xor_sync(0xffffffffu, var, 2);
    const float rstd = rsqrtf(var * (1.f / 64.f) + 1e-6f);
    const float4* gp = (const float4*)(g + c0);
    const float4* bp = (const float4*)(bb + c0);
    float4* op = (float4*)(Out + r * LD + c0);
    float4 xv, gv, bv4, ov;
    #pragma unroll
    for (int q = 0; q < 4; q++) {
        xv = (q==0)?v0:((q==1)?v1:((q==2)?v2:v3));
        gv = gp[q]; bv4 = bp[q];
        ov.x = gv.x * (xv.x - mu) * rstd + bv4.x;
        ov.y = gv.y * (xv.y - mu) * rstd + bv4.y;
        ov.z = gv.z * (xv.z - mu) * rstd + bv4.z;
        ov.w = gv.w * (xv.w - mu) * rstd + bv4.w;
        op[q] = ov;
    }
}

__global__ __launch_bounds__(256, 2) void fsa_kernel(
    const int*   __restrict__ tok_g,
    const float* __restrict__ emb,
    const float* __restrict__ np_w,   const float* __restrict__ np_b,
    const float* __restrict__ grp_ln_g, const float* __restrict__ grp_ln_b,
    const float* __restrict__ attn_b,
    const float* __restrict__ ln1_g,  const float* __restrict__ ln1_b,
    const float* __restrict__ ln2_g,  const float* __restrict__ ln2_b,
    const float* __restrict__ ffn_w1,
    const float* __restrict__ ffn_b1, const float* __restrict__ ffn_b2,
    const float* __restrict__ enc_g,  const float* __restrict__ enc_b,
    const float* __restrict__ red_w,  const float* __restrict__ red_b,
    const float* __restrict__ opc_w,  const float* __restrict__ opc_b,
    const float* __restrict__ res_w,  const float* __restrict__ res_b,
    float* __restrict__ out, int out_size)
{
    extern __shared__ float smraw[];
    Smem& sm = *reinterpret_cast<Smem*>(smraw);
    const int b   = blockIdx.x;
    const int tid = threadIdx.x;

    if (tid < 64) {
        int t = tok_g[b * 64 + tid];
        sm.tok[tid] = t;
        sm.m0[tid]  = (t != 0) ? 1.f : 0.f;
        float isd   = (t >= 4 && t <= 13) ? 1.f : 0.f;
        sm.isd[tid] = isd;
        sm.dv[tid]  = ((float)t - 4.f) * isd;
    }
    __syncthreads();

    unsigned mbit0, mbit1;
    {
        int lane = tid & 31;
        mbit0 = __ballot_sync(0xffffffffu, sm.m0[lane] > 0.f);
        mbit1 = __ballot_sync(0xffffffffu, sm.m0[lane + 32] > 0.f);
    }

    {
        const int r = tid >> 2, c0 = (tid & 3) * 16;
        const int t = sm.tok[r];
        const float isd  = sm.isd[r];
        const float dvv  = sm.dv[r];
        const float isop = (t >= 14 && t <= 17) ? 1.f : 0.f;
        const float opt  = isop * ((float)t - 13.f);
        const float* erow = emb + t * 64;
        const float kfreq2 = (float)(-13.287712379549449 / 64.0);
        #pragma unroll 4
        for (int c = 0; c < 16; c++) {
            int cc = c0 + c;
            float base = erow[cc] * 8.f
                       + dvv  * np_w[cc]       + isd  * np_w[64 + cc]
                       + opt  * np_w[128 + cc] + isop * np_w[192 + cc]
                       + np_b[cc];
            float freq = ex2f((float)(cc & ~1) * kfreq2);
            float ang  = (float)r * freq;
            float pe   = (cc & 1) ? __cosf(ang) : __sinf(ang);
            sm.X[r * LD + cc] = base + pe;
        }
    }
    __syncthreads();

    float* const Kb = sm.KV;
    float* const Vb = sm.KV + 64 * LD;

    #pragma unroll 1
    for (int l = 0; l < 2; l++) {
        // ---- group attention -> G (via Z = C·M, M = Wq·Wk^T precomputed) ----
        layernorm(sm.X, grp_ln_g + l * 64, grp_ln_b + l * 64, sm.A, tid);
        __syncthreads();
        gemm2d_single<64,false,false>(sm.A, LD, g_wpack + CC_GRPM + l*4096,
                                      g_wpack + CC_ZERO, sm.Bf, LD, tid);
        if (tid < 64) {   // pu = c_i·u , pw = c_i·w
            const ulonglong2* cr = (const ulonglong2*)(sm.A + tid * LD);
            const ulonglong2* up = (const ulonglong2*)(g_wpack + CC_U + l*64);
            const ulonglong2* wp = (const ulonglong2*)(g_wpack + CC_W + l*64);
            ull au = 0ull, aw = 0ull;
            #pragma unroll 4
            for (int m = 0; m < 16; m++) {
                ulonglong2 c = cr[m], uu = up[m], ww = wp[m];
                au = ffma2(c.x, uu.x, au); au = ffma2(c.y, uu.y, au);
                aw = ffma2(c.x, ww.x, aw); aw = ffma2(c.y, ww.y, aw);
            }
            float2 pu = unpack2(au), pw = unpack2(aw);
            sm.pmL[tid] = pu.x + pu.y;
            sm.pmR[tid] = pw.x + pw.y;
        }
        __syncthreads();
        // tridiagonal scores: s(i,j) = Z_i·c_j + pu_i + pw_j + K0
        if (tid < 63 || (tid >= 64 && tid < 127)) {
            const int up = (tid < 63);
            const int i  = up ? tid : (tid - 64);
            const ulonglong2* zp = (const ulonglong2*)(sm.Bf + (up ? i : i + 1) * LD);
            const ulonglong2* cp = (const ulonglong2*)(sm.A  + (up ? i + 1 : i) * LD);
            ull acc = 0ull;
            #pragma unroll 4
            for (int m = 0; m < 16; m++) {
                ulonglong2 z4 = zp[m], c4 = cp[m];
                acc = ffma2(z4.x, c4.x, acc);
                acc = ffma2(z4.y, c4.y, acc);
            }
            float2 p = unpack2(acc);
            float extra = up ? (sm.pmL[i] + sm.pmR[i + 1])
                             : (sm.pmL[i + 1] + sm.pmR[i]);
            float sv = (p.x + p.y + extra + g_wpack[CC_K0 + l]) * SGRP;
            if (up) sm.s1[i] = sv; else sm.s2[i] = sv;
        }
        __syncthreads();
        if (tid < 64) {
            const int i = tid;
            const float m_i = sm.m0[i];
            bool vL = (i > 0)  && m_i > 0.f && sm.m0[i-1] > 0.f;
            bool vR = (i < 63) && m_i > 0.f && sm.m0[i+1] > 0.f;
            float pr_i, ps_i;
            if (!vL && !vR) { pr_i = 1.f/64.f; ps_i = 1.f/64.f; }
            else {
                float sL = vL ? sm.s2[i-1] : -3.4e38f;
                float sR = vR ? sm.s1[i]   : -3.4e38f;
                float m  = fmaxf(sL, sR);
                float eL = vL ? ex2f(sL - m) : 0.f;
                float eR = vR ? ex2f(sR - m) : 0.f;
                pr_i = eR / (eL + eR); ps_i = 0.f;
            }
            float nbd = sqrtf(ps_i * ps_i + 1e-9f);
            if (l > 0) { float pp = sm.G[i * LD + i]; nbd = pp + (1.f - pp) * nbd; }
            sm.q1[i] = nbd;
            if (i < 63) {
                const int i1 = i + 1;
                bool vL1 = m_i > 0.f && sm.m0[i1] > 0.f;
                bool vR1 = (i1 < 63) && sm.m0[i1] > 0.f && sm.m0[i1+1] > 0.f;
                float pl1;
                if (!vL1 && !vR1) pl1 = 1.f/64.f;
                else {
                    float sL = vL1 ? sm.s2[i]  : -3.4e38f;
                    float sR = vR1 ? sm.s1[i1] : -3.4e38f;
                    float m  = fmaxf(sL, sR);
                    float eL = vL1 ? ex2f(sL - m) : 0.f;
                    float eR = vR1 ? ex2f(sR - m) : 0.f;
                    pl1 = eL / (eL + eR);
                }
                float nbu = sqrtf(pr_i * pl1 + 1e-9f);
                if (l > 0) { float pp = sm.G[i * LD + i1]; nbu = pp + (1.f - pp) * nbu; }
                sm.q2[i] = lg2f_(nbu + 1e-9f);
            } else {
                sm.q2[63] = 0.f;
            }
        }
        __syncthreads();
        if (tid < 32) {   // exclusive scan of q2 -> S
            float a0 = sm.q2[2*tid], a1 = sm.q2[2*tid+1];
            float p = a0 + a1;
            #pragma unroll
            for (int d = 1; d < 32; d <<= 1) {
                float tshf = __shfl_up_sync(0xffffffffu, p, d);
                if ((int)tid >= d) p += tshf;
            }
            sm.S[2*tid+1] = p - a1;
            if (tid < 31) sm.S[2*tid+2] = p;
            if (tid == 0) sm.S[0] = 0.f;
        }
        __syncthreads();
        for (int t = tid; t < 4096; t += 256) {
            int i = t >> 6, j = t & 63;
            float v;
            if (i == j) v = sm.q1[i];
            else {
                int lo = (i < j) ? i : j, hi2 = (i < j) ? j : i;
                v = ex2f(sm.S[hi2] - sm.S[lo]) + 1e-9f;
            }
            sm.G[i * LD + j] = v;
        }
        __syncthreads();

        // ---- multi-head attention ----
        layernorm(sm.X, ln1_g + l * 64, ln1_b + l * 64, sm.A, tid);
        __syncthreads();
        gemm2d_dual<false>(sm.A, LD, g_wpack + CC_AQK + l*8192,
                           attn_b + (l*4+0)*64, attn_b + (l*4+1)*64, sm.Bf, Kb, LD, tid);
        gemm2d_single<64,false,false>(sm.A, LD, g_wpack + CC_V + l*4096,
                                      attn_b + (l*4+2)*64, Vb, LD, tid);
        __syncthreads();
        // fused attention: thread = (head, row); unnormalized softmax single pass
        {
            const int warp = tid >> 5, lane = tid & 31;
            const int h = warp >> 1;
            const int r = (warp & 1) * 32 + lane;
            const ull satt2 = pack2(SATT, SATT);
            const ulonglong2* qp = (const ulonglong2*)(sm.Bf + r * LD + h * 16);
            ulonglong2 qA = qp[0], qB = qp[1], qC = qp[2], qD = qp[3];
            qA.x = mul2(qA.x, satt2); qA.y = mul2(qA.y, satt2);
            qB.x = mul2(qB.x, satt2); qB.y = mul2(qB.y, satt2);
            qC.x = mul2(qC.x, satt2); qC.y = mul2(qC.y, satt2);
            qD.x = mul2(qD.x, satt2); qD.y = mul2(qD.y, satt2);
            ull o[8];
            #pragma unroll
            for (int k = 0; k < 8; k++) o[k] = 0ull;
            float Z = 0.f;
            #pragma unroll 4
            for (int j = 0; j < 64; j++) {
                const ulonglong2* kp = (const ulonglong2*)(Kb + j * LD + h * 16);
                ulonglong2 kA = kp[0], kB = kp[1], kC = kp[2], kD = kp[3];
                ull acc = 0ull;
                acc = ffma2(qA.x, kA.x, acc);
                acc = ffma2(qA.y, kA.y, acc);
                acc = ffma2(qB.x, kB.x, acc);
                acc = ffma2(qB.y, kB.y, acc);
                acc = ffma2(qC.x, kC.x, acc);
                acc = ffma2(qC.y, kC.y, acc);
                acc = ffma2(qD.x, kD.x, acc);
                acc = ffma2(qD.y, kD.y, acc);
                float2 p = unpack2(acc);
                unsigned vbit = (j < 32) ? (mbit0 >> j) : (mbit1 >> (j - 32));
                float e = (vbit & 1u) ? ex2f(p.x + p.y) : 0.f;
                Z += e;
                float w = e * sm.G[j * LD + r];
                ull wb = pack2(w, w);
                const ulonglong2* vp = (const ulonglong2*)(Vb + j * LD + h * 16);
                ulonglong2 vA = vp[0], vB = vp[1], vC = vp[2], vD = vp[3];
                o[0] = ffma2(wb, vA.x, o[0]); o[1] = ffma2(wb, vA.y, o[1]);
                o[2] = ffma2(wb, vB.x, o[2]); o[3] = ffma2(wb, vB.y, o[3]);
                o[4] = ffma2(wb, vC.x, o[4]); o[5] = ffma2(wb, vC.y, o[5]);
                o[6] = ffma2(wb, vD.x, o[6]); o[7] = ffma2(wb, vD.y, o[7]);
            }
            if (Z == 0.f) {   // all-masked row: reference softmax uniform 1/64
                #pragma unroll
                for (int k = 0; k < 8; k++) o[k] = 0ull;
                for (int j = 0; j < 64; j++) {
                    float w = sm.G[j * LD + r] * 0.015625f;
                    ull wb = pack2(w, w);
                    const ulonglong2* vp = (const ulonglong2*)(Vb + j * LD + h * 16);
                    ulonglong2 vA = vp[0], vB = vp[1], vC = vp[2], vD = vp[3];
                    o[0] = ffma2(wb, vA.x, o[0]); o[1] = ffma2(wb, vA.y, o[1]);
                    o[2] = ffma2(wb, vB.x, o[2]); o[3] = ffma2(wb, vB.y, o[3]);
                    o[4] = ffma2(wb, vC.x, o[4]); o[5] = ffma2(wb, vC.y, o[5]);
                    o[6] = ffma2(wb, vD.x, o[6]); o[7] = ffma2(wb, vD.y, o[7]);
                }
                Z = 1.f;
            }
            const float invZ = 1.f / Z;
            const ull zb = pack2(invZ, invZ);
            float* op = sm.Bf + r * LD + h * 16;
            #pragma unroll
            for (int k = 0; k < 4; k++) {
                float2 pa = unpack2(mul2(o[2*k],   zb));
                float2 pb = unpack2(mul2(o[2*k+1], zb));
                float4 st; st.x = pa.x; st.y = pa.y; st.z = pb.x; st.w = pb.y;
                *(float4*)(op + 4*k) = st;
            }
        }
        __syncthreads();
        gemm2d_single<64,false,true>(sm.Bf, LD, g_wpack + CC_O + l*4096,
                                     attn_b + (l*4+3)*64, sm.X, LD, tid);
        __syncthreads();

        // ---- FFN ----
        layernorm(sm.X, ln2_g + l * 64, ln2_b + l * 64, sm.A, tid);
        __syncthreads();
        gemm2d_dual<true>(sm.A, LD, ffn_w1 + l*8192,
                          ffn_b1 + l*128, ffn_b1 + l*128 + 64, sm.KV, sm.KV + 64, LDF, tid);
        __syncthreads();
        gemm2d_single<128,false,true>(sm.KV, LDF, g_wpack + CC_FFN2 + l*8192,
                                      ffn_b2 + l*64, sm.X, LD, tid);
        __syncthreads();
    }

    // ================= readout =================
    layernorm(sm.X, enc_g, enc_b, sm.A, tid);
    __syncthreads();
    if (tid < 64) {
        const ulonglong2* xr = (const ulonglong2*)(sm.A + tid * LD);
        const ulonglong2* wr = (const ulonglong2*)red_w;
        ull acc = 0ull;
        #pragma unroll 4
        for (int m = 0; m < 16; m++) {
            ulonglong2 x4 = xr[m], w4 = wr[m];
            acc = ffma2(x4.x, w4.x, acc);
            acc = ffma2(x4.y, w4.y, acc);
        }
        float2 p = unpack2(acc);
        float s = p.x + p.y + red_b[0];
        s += (1.f - sm.m0[tid]) * (-1e9f);
        sm.s1[tid] = s;
    }
    __syncthreads();
    if (tid < 32) {
        float m = fmaxf(sm.s1[tid], sm.s1[tid + 32]);
        #pragma unroll
        for (int d = 16; d >= 1; d >>= 1) m = fmaxf(m, __shfl_xor_sync(0xffffffffu, m, d));
        if (tid == 0) sm.scal[0] = m;
    }
    __syncthreads();
    if (tid < 64) sm.s2[tid] = ex2f((sm.s1[tid] - sm.scal[0]) * LOG2E);
    __syncthreads();
    if (tid < 32) {
        float z = sm.s2[tid] + sm.s2[tid + 32];
        #pragma unroll
        for (int d = 16; d >= 1; d >>= 1) z += __shfl_xor_sync(0xffffffffu, z, d);
        if (tid == 0) sm.scal[1] = z;
    }
    __syncthreads();
    if (tid < 64) sm.rw[tid] = sm.s2[tid] / sm.scal[1];
    __syncthreads();
    if (tid < 32) {
        float a0 = sm.rw[2*tid], a1 = sm.rw[2*tid+1];
        float p = a0 + a1;
        #pragma unroll
        for (int d = 1; d < 32; d <<= 1) {
            float tshf = __shfl_up_sync(0xffffffffu, p, d);
            if ((int)tid >= d) p += tshf;
        }
        sm.cum[2*tid+1] = p;
        sm.cum[2*tid]   = p - a1;
    }
    __syncthreads();
    if (tid < 64) {
        sm.pmL[tid] = (1.f - sm.cum[tid]) * sm.isd[tid];
        sm.pmR[tid] = (sm.cum[tid] - sm.rw[tid]) * sm.isd[tid];
    }
    if (tid >= 64 && tid < 128) {
        int h = tid - 64;
        float p = 0.f;
        #pragma unroll 8
        for (int ll = 0; ll < 64; ll++) p = fmaf(sm.A[ll * LD + h], sm.rw[ll], p);
        sm.pooled[h] = p;
    }
    __syncthreads();
    if (tid < 64) {
        const int lane = tid & 31;
        const float* pm = (tid < 32) ? sm.pmL : sm.pmR;
        float a0 = pm[2*lane], a1 = pm[2*lane+1];
        float p = a0 + a1;
        #pragma unroll
        for (int d = 1; d < 32; d <<= 1) {
            float tshf = __shfl_up_sync(0xffffffffu, p, d);
            if (lane >= d) p += tshf;
        }
        float tot  = __shfl_sync(0xffffffffu, p, 31);
        float run1 = p, run0 = p - a1;
        float d0 = sm.dv[2*lane], d1 = sm.dv[2*lane+1];
        float acc = d0 * ex2f((tot - run0) * a0 * LOG2_10) * a0
                  + d1 * ex2f((tot - run1) * a1 * LOG2_10) * a1;
        #pragma unroll
        for (int d = 16; d >= 1; d >>= 1) acc += __shfl_xor_sync(0xffffffffu, acc, d);
        if (lane == 0) sm.scal[(tid < 32) ? 5 : 6] = acc;
    } else if (tid >= 64 && tid < 96) {
        const int lane = tid & 31;
        float p0 = sm.pooled[lane], p1 = sm.pooled[lane + 32];
        float l0 = p0 * opc_w[lane*4+0] + p1 * opc_w[(lane+32)*4+0];
        float l1 = p0 * opc_w[lane*4+1] + p1 * opc_w[(lane+32)*4+1];
        float l2 = p0 * opc_w[lane*4+2] + p1 * opc_w[(lane+32)*4+2];
        float l3 = p0 * opc_w[lane*4+3] + p1 * opc_w[(lane+32)*4+3];
        #pragma unroll
        for (int d = 16; d >= 1; d >>= 1) {
            l0 += __shfl_xor_sync(0xffffffffu, l0, d);
            l1 += __shfl_xor_sync(0xffffffffu, l1, d);
            l2 += __shfl_xor_sync(0xffffffffu, l2, d);
            l3 += __shfl_xor_sync(0xffffffffu, l3, d);
        }
        if (lane == 0) {
            sm.s1[0] = l0 + opc_b[0];
            sm.s1[1] = l1 + opc_b[1];
            sm.s1[2] = l2 + opc_b[2];
            sm.s1[3] = l3 + opc_b[3];
        }
    }
    __syncthreads();
    if (tid == 0) {
        float lv = sm.scal[5], rv = sm.scal[6];
        float lg0 = sm.s1[0], lg1 = sm.s1[1], lg2 = sm.s1[2], lg3 = sm.s1[3];
        int op = 0; float bm = lg0;
        if (lg1 > bm) { bm = lg1; op = 1; }
        if (lg2 > bm) { bm = lg2; op = 2; }
        if (lg3 > bm) { bm = lg3; op = 3; }
        float result, valid = 1.f;
        if      (op == 0) result = lv + rv;
        else if (op == 1) result = lv - rv;
        else if (op == 2) result = lv * rv;
        else {
            bool bad = fabsf(rv) < 1e-6f;
            result = bad ? 0.f : lv / rv;
            valid  = bad ? 0.f : 1.f;
        }
        float sgn = (result > 0.f) ? 1.f : ((result < 0.f) ? -1.f : 0.f);
        float rc  = sgn * log1pf(fabsf(result));
        sm.scal[2] = result; sm.scal[3] = valid; sm.scal[4] = rc;
    }
    __syncthreads();

    const bool full = (out_size >= 136 * NB);
    if (full) {
        if (tid == 0) {
            out[b]           = sm.scal[2];
            out[65*NB + b]   = sm.scal[3];
            out[66*NB + b]   = sm.scal[5];
            out[67*NB + b]   = sm.scal[6];
            #pragma unroll
            for (int o = 0; o < 4; o++) out[68*NB + b*4 + o] = sm.s1[o];
        }
        if (tid < 64) {
            float rc = sm.scal[4], valid = sm.scal[3];
            out[NB + b*64 + tid]    = rc * res_w[tid] + valid * res_w[64 + tid] + res_b[tid];
            out[72*NB + b*64 + tid] = sm.rw[tid];
        }
    } else {
        if (tid == 0) out[b] = sm.scal[2];
    }
}

extern "C" void kernel_launch(void* const* d_in, const int* in_sizes, int n_in,
                              void* d_out, int out_size)
{
    pack_weights<<<(WP_TOTAL + 255) / 256, 256>>>(
        (const float*)d_in[4],   // grp_wq
        (const float*)d_in[6],   // grp_wk
        (const float*)d_in[5],   // grp_bq
        (const float*)d_in[7],   // grp_bk
        (const float*)d_in[10],  // attn_w
        (const float*)d_in[18]); // ffn_w2

    const size_t shmem = sizeof(Smem);
    cudaFuncSetAttribute(fsa_kernel, cudaFuncAttributeMaxDynamicSharedMemorySize, (int)shmem);
    fsa_kernel<<<NB, 256, shmem>>>(
        (const int*)  d_in[0],
        (const float*)d_in[1],
        (const float*)d_in[2],  (const float*)d_in[3],    // np_w, np_b
        (const float*)d_in[8],  (const float*)d_in[9],    // grp_ln_g, grp_ln_b
        (const float*)d_in[11],                            // attn_b
        (const float*)d_in[12], (const float*)d_in[13],   // ln1_g, ln1_b
        (const float*)d_in[14], (const float*)d_in[15],   // ln2_g, ln2_b
        (const float*)d_in[16],                            // ffn_w1
        (const float*)d_in[17], (const float*)d_in[19],   // ffn_b1, ffn_b2
        (const float*)d_in[20], (const float*)d_in[21],   // enc_g, enc_b
        (const float*)d_in[22], (const float*)d_in[23],   // red_w, red_b
        (const float*)d_in[24], (const float*)d_in[25],   // opc_w, opc_b
        (const float*)d_in[26], (const float*)d_in[27],   // res_w, res_b
        (float*)d_out, out_size);
}

// round 16
// speedup vs baseline: 1.1459x; 1.0197x over previous
#include <cuda_runtime.h>
#include <math.h>

#define NB   4096
#define LD   68
#define LDF  132

typedef unsigned long long ull;

__device__ __forceinline__ float2 unpack2(ull v) {
    float2 r; asm("mov.b64 {%0, %1}, %2;" : "=f"(r.x), "=f"(r.y) : "l"(v)); return r;
}
__device__ __forceinline__ ull pack2(float x, float y) {
    ull r; asm("mov.b64 %0, {%1, %2};" : "=l"(r) : "f"(x), "f"(y)); return r;
}
__device__ __forceinline__ ull ffma2(ull a, ull b, ull c) {
    ull r; asm("fma.rn.f32x2 %0, %1, %2, %3;" : "=l"(r) : "l"(a), "l"(b), "l"(c)); return r;
}
__device__ __forceinline__ ull mul2(ull a, ull b) {
    ull r; asm("mul.rn.f32x2 %0, %1, %2;" : "=l"(r) : "l"(a), "l"(b)); return r;
}
__device__ __forceinline__ float ex2f(float x) {
    float r; asm("ex2.approx.f32 %0, %1;" : "=f"(r) : "f"(x)); return r;
}
__device__ __forceinline__ float lg2f_(float x) {
    float r; asm("lg2.approx.f32 %0, %1;" : "=f"(r) : "f"(x)); return r;
}

#define LOG2E    1.4426950408889634f
#define LOG2_10  3.3219280948873623f
#define SGRP     (0.125f * LOG2E)
#define SATT     (0.25f  * LOG2E)

// ---------------- packed weights (identical to R13/R15) ----------------
#define CC_GRPM  0        // 2 x 4096 (M = Wq·Wk^T pairs)
#define CC_U     8192     // 2 x 64
#define CC_W     8320     // 2 x 64
#define CC_K0    8448     // 2 (+pad to 64)
#define CC_ZERO  8512     // 64 zeros
#define CC_AQK   8576     // 2 x 8192 (attn Q|K concat [k][128])
#define CC_V     24960    // 2 x 4096 (pairs)
#define CC_O     33152    // 2 x 4096
#define CC_FFN2  41344    // 2 x 8192
#define WP_TOTAL 57728
__device__ float g_wpack[WP_TOTAL];

__global__ void pack_weights(const float* __restrict__ grp_wq,
                             const float* __restrict__ grp_wk,
                             const float* __restrict__ grp_bq,
                             const float* __restrict__ grp_bk,
                             const float* __restrict__ attn_w,
                             const float* __restrict__ ffn_w2)
{
    int idx = blockIdx.x * 256 + threadIdx.x;
    if (idx >= WP_TOTAL) return;
    float v;
    if (idx < CC_U) {
        int off = idx;           int l = off >> 12; int r = off & 4095;
        int kk = r >> 7; int t = r & 127; int j = t >> 1; int s = t & 1;
        const float* wq = grp_wq + l*4096 + (2*kk + s)*64;
        const float* wk = grp_wk + l*4096 + j*64;
        float acc = 0.f;
        for (int d = 0; d < 64; d++) acc = fmaf(wq[d], wk[d], acc);
        v = acc;
    } else if (idx < CC_W) {
        int off = idx - CC_U;    int l = off >> 6; int i = off & 63;
        const float* wq = grp_wq + l*4096 + i*64;
        const float* bk = grp_bk + l*64;
        float acc = 0.f;
        for (int d = 0; d < 64; d++) acc = fmaf(wq[d], bk[d], acc);
        v = acc;
    } else if (idx < CC_K0) {
        int off = idx - CC_W;    int l = off >> 6; int i = off & 63;
        const float* wk = grp_wk + l*4096 + i*64;
        const float* bq = grp_bq + l*64;
        float acc = 0.f;
        for (int d = 0; d < 64; d++) acc = fmaf(wk[d], bq[d], acc);
        v = acc;
    } else if (idx < CC_ZERO) {
        int off = idx - CC_K0;
        if (off < 2) {
            const float* bq = grp_bq + off*64;
            const float* bk = grp_bk + off*64;
            float acc = 0.f;
            for (int d = 0; d < 64; d++) acc = fmaf(bq[d], bk[d], acc);
            v = acc;
        } else v = 0.f;
    } else if (idx < CC_AQK) {
        v = 0.f;
    } else if (idx < CC_V) {
        int off = idx - CC_AQK;  int l = off >> 13; int r = off & 8191;
        int k = r >> 7; int c = r & 127;
        v = attn_w[(l*4 + (c>>6))*4096 + k*64 + (c&63)];
    } else if (idx < CC_O) {
        int off = idx - CC_V;    int l = off >> 12; int r = off & 4095;
        int kk = r >> 7; int t = r & 127; int j = t >> 1; int s = t & 1;
        v = attn_w[(l*4+2)*4096 + (2*kk+s)*64 + j];
    } else if (idx < CC_FFN2) {
        int off = idx - CC_O;    int l = off >> 12; int r = off & 4095;
        int kk = r >> 7; int t = r & 127; int j = t >> 1; int s = t & 1;
        v = attn_w[(l*4+3)*4096 + (2*kk+s)*64 + j];
    } else {
        int off = idx - CC_FFN2; int l = off >> 13; int r = off & 8191;
        int kk = r >> 7; int t = r & 127; int j = t >> 1; int s = t & 1;
        v = ffn_w2[l*8192 + (2*kk+s)*64 + j];
    }
    g_wpack[idx] = v;
}

struct Smem {
    float X [64*LD];
    float A [64*LD];
    float Bf[64*LD];
    float KV[2*64*LD];
    float m0[64], dv[64], isd[64];
    float s1[64], s2[64];
    float q1[64], q2[64], S[64];
    float rw[64], cum[64], pooled[64], pmL[64], pmR[64];
    int   tok[64];
    float scal[8];
};

// ---- dual gemm on 2x4 warp grid: A(64x64) @ W[64][128] -> Out0|Out1
#define DROW(t, av) \
    acc[t][0] = fmaf(av, w.x, acc[t][0]); \
    acc[t][1] = fmaf(av, w.y, acc[t][1]); \
    acc[t][2] = fmaf(av, w.z, acc[t][2]); \
    acc[t][3] = fmaf(av, w.w, acc[t][3]);

#define DALL(comp) \
    DROW(0, a[0].comp) DROW(1, a[1].comp) DROW(2, a[2].comp) DROW(3, a[3].comp) \
    DROW(4, a[4].comp) DROW(5, a[5].comp) DROW(6, a[6].comp) DROW(7, a[7].comp)

template<bool RELU>
__device__ __forceinline__ void gemm2d_dual(const float* __restrict__ Am, int lda,
                                            const float* __restrict__ W,   // ldw=128
                                            const float* __restrict__ bias0,
                                            const float* __restrict__ bias1,
                                            float* __restrict__ Out0,
                                            float* __restrict__ Out1,
                                            int ldo, int tid)
{
    const int warp = tid >> 5, lane = tid & 31;
    const int ly = lane >> 3, lx = lane & 7;
    const int wm = warp >> 2, wn = warp & 3;
    const int rbase = wm * 32 + ly;
    const int c0 = wn * 32 + lx * 4;
    float acc[8][4];
    #pragma unroll
    for (int t = 0; t < 8; t++)
        #pragma unroll
        for (int c = 0; c < 4; c++) acc[t][c] = 0.f;

    #pragma unroll 2
    for (int kq = 0; kq < 16; kq++) {
        float4 a[8];
        #pragma unroll
        for (int t = 0; t < 8; t++)
            a[t] = *(const float4*)(Am + (rbase + 4*t) * lda + 4*kq);
        { float4 w = *(const float4*)(W + (4*kq + 0) * 128 + c0); DALL(x) }
        { float4 w = *(const float4*)(W + (4*kq + 1) * 128 + c0); DALL(y) }
        { float4 w = *(const float4*)(W + (4*kq + 2) * 128 + c0); DALL(z) }
        { float4 w = *(const float4*)(W + (4*kq + 3) * 128 + c0); DALL(w) }
    }
    const float* bp = (c0 < 64) ? (bias0 + c0) : (bias1 + c0 - 64);
    float* ob       = (c0 < 64) ? (Out0 + c0)  : (Out1 + c0 - 64);
    float4 bv = *(const float4*)bp;
    #pragma unroll
    for (int t = 0; t < 8; t++) {
        float4 st;
        st.x = acc[t][0] + bv.x; st.y = acc[t][1] + bv.y;
        st.z = acc[t][2] + bv.z; st.w = acc[t][3] + bv.w;
        if (RELU) {
            st.x = fmaxf(st.x, 0.f); st.y = fmaxf(st.y, 0.f);
            st.z = fmaxf(st.z, 0.f); st.w = fmaxf(st.w, 0.f);
        }
        *(float4*)(ob + (rbase + 4*t) * ldo) = st;
    }
}

// ---- single gemm on 4x2 warp grid with k-interleaved packed W
template<int K, bool RELU, bool RES>
__device__ __forceinline__ void gemm2d_single(const float* __restrict__ Am, int lda,
                                              const float* __restrict__ Wp,
                                              const float* __restrict__ bias,
                                              float* __restrict__ Out, int ldo, int tid)
{
    const int warp = tid >> 5, lane = tid & 31;
    const int ly = lane >> 3, lx = lane & 7;
    const int wm = warp >> 1, wn = warp & 1;
    const int rbase = wm * 16 + ly;
    const int c0 = wn * 32 + lx * 4;
    ull acc[4][4];
    #pragma unroll
    for (int t = 0; t < 4; t++)
        #pragma unroll
        for (int c = 0; c < 4; c++) acc[t][c] = 0ull;

    #pragma unroll 4
    for (int kq = 0; kq < K/4; kq++) {
        ulonglong2 a[4];
        #pragma unroll
        for (int t = 0; t < 4; t++)
            a[t] = *(const ulonglong2*)(Am + (rbase + 4*t) * lda + 4*kq);
        const float* wb0 = Wp + ((2*kq    ) * 64 + c0) * 2;
        const float* wb1 = Wp + ((2*kq + 1) * 64 + c0) * 2;
        ulonglong2 w00 = *(const ulonglong2*)(wb0);
        ulonglong2 w01 = *(const ulonglong2*)(wb0 + 4);
        ulonglong2 w10 = *(const ulonglong2*)(wb1);
        ulonglong2 w11 = *(const ulonglong2*)(wb1 + 4);
        #pragma unroll
        for (int t = 0; t < 4; t++) {
            acc[t][0] = ffma2(a[t].x, w00.x, acc[t][0]);
            acc[t][1] = ffma2(a[t].x, w00.y, acc[t][1]);
            acc[t][2] = ffma2(a[t].x, w01.x, acc[t][2]);
            acc[t][3] = ffma2(a[t].x, w01.y, acc[t][3]);
            acc[t][0] = ffma2(a[t].y, w10.x, acc[t][0]);
            acc[t][1] = ffma2(a[t].y, w10.y, acc[t][1]);
            acc[t][2] = ffma2(a[t].y, w11.x, acc[t][2]);
            acc[t][3] = ffma2(a[t].y, w11.y, acc[t][3]);
        }
    }
    float4 bv = *(const float4*)(bias + c0);
    #pragma unroll
    for (int t = 0; t < 4; t++) {
        float2 p0 = unpack2(acc[t][0]);
        float2 p1 = unpack2(acc[t][1]);
        float2 p2 = unpack2(acc[t][2]);
        float2 p3 = unpack2(acc[t][3]);
        float4 st;
        st.x = p0.x + p0.y + bv.x;
        st.y = p1.x + p1.y + bv.y;
        st.z = p2.x + p2.y + bv.z;
        st.w = p3.x + p3.y + bv.w;
        if (RELU) {
            st.x = fmaxf(st.x, 0.f); st.y = fmaxf(st.y, 0.f);
            st.z = fmaxf(st.z, 0.f); st.w = fmaxf(st.w, 0.f);
        }
        float* op = Out + (rbase + 4*t) * ldo + c0;
        if (RES) {
            float4 old = *(float4*)op;
            st.x += old.x; st.y += old.y; st.z += old.z; st.w += old.w;
        }
        *(float4*)op = st;
    }
}

__device__ __forceinline__ void layernorm(const float* __restrict__ Xm,
                                          const float* __restrict__ g,
                                          const float* __restrict__ bb,
                                          float* __restrict__ Out, int tid)
{
    const int r = tid >> 2, c0 = (tid & 3) * 16;
    const float4* xr = (const float4*)(Xm + r * LD + c0);
    float4 v0 = xr[0], v1 = xr[1], v2 = xr[2], v3 = xr[3];
    float s = v0.x+v0.y+v0.z+v0.w + v1.x+v1.y+v1.z+v1.w
            + v2.x+v2.y+v2.z+v2.w + v3.x+v3.y+v3.z+v3.w;
    s += __shfl_xor_sync(0xffffffffu, s, 1);
    s += __shfl_xor_sync(0xffffffffu, s, 2);
    const float mu = s * (1.f / 64.f);
    float var = 0.f;
    {
        float d;
        d = v0.x - mu; var += d*d;  d = v0.y - mu; var += d*d;
        d = v0.z - mu; var += d*d;  d = v0.w - mu; var += d*d;
        d = v1.x - mu; var += d*d;  d = v1.y - mu; var += d*d;
        d = v1.z - mu; var += d*d;  d = v1.w - mu; var += d*d;
        d = v2.x - mu; var += d*d;  d = v2.y - mu; var += d*d;
        d = v2.z - mu; var += d*d;  d = v2.w - mu; var += d*d;
        d = v3.x - mu; var += d*d;  d = v3.y - mu; var += d*d;
        d = v3.z - mu; var += d*d;  d = v3.w - mu; var += d*d;
    }
    var += __shfl_xor_sync(0xffffffffu, var, 1);
    var += __shfl_xor_sync(0xffffffffu, var, 2);
    const float rstd = rsqrtf(var * (1.f / 64.f) + 1e-6f);
    const float4* gp = (const float4*)(g + c0);
    const float4* bp = (const float4*)(bb + c0);
    float4* op = (float4*)(Out + r * LD + c0);
    float4 xv, gv, bv4, ov;
    #pragma unroll
    for (int q = 0; q < 4; q++) {
        xv = (q==0)?v0:((q==1)?v1:((q==2)?v2:v3));
        gv = gp[q]; bv4 = bp[q];
        ov.x = gv.x * (xv.x - mu) * rstd + bv4.x;
        ov.y = gv.y * (xv.y - mu) * rstd + bv4.y;
        ov.z = gv.z * (xv.z - mu) * rstd + bv4.z;
        ov.w = gv.w * (xv.w - mu) * rstd + bv4.w;
        op[q] = ov;
    }
}

__global__ __launch_bounds__(256, 2) void fsa_kernel(
    const int*   __restrict__ tok_g,
    const float* __restrict__ emb,
    const float* __restrict__ np_w,   const float* __restrict__ np_b,
    const float* __restrict__ grp_ln_g, const float* __restrict__ grp_ln_b,
    const float* __restrict__ attn_b,
    const float* __restrict__ ln1_g,  const float* __restrict__ ln1_b,
    const float* __restrict__ ln2_g,  const float* __restrict__ ln2_b,
    const float* __restrict__ ffn_w1,
    const float* __restrict__ ffn_b1, const float* __restrict__ ffn_b2,
    const float* __restrict__ enc_g,  const float* __restrict__ enc_b,
    const float* __restrict__ red_w,  const float* __restrict__ red_b,
    const float* __restrict__ opc_w,  const float* __restrict__ opc_b,
    const float* __restrict__ res_w,  const float* __restrict__ res_b,
    float* __restrict__ out, int out_size)
{
    extern __shared__ float smraw[];
    Smem& sm = *reinterpret_cast<Smem*>(smraw);
    const int b   = blockIdx.x;
    const int tid = threadIdx.x;

    if (tid < 64) {
        int t = tok_g[b * 64 + tid];
        sm.tok[tid] = t;
        sm.m0[tid]  = (t != 0) ? 1.f : 0.f;
        float isd   = (t >= 4 && t <= 13) ? 1.f : 0.f;
        sm.isd[tid] = isd;
        sm.dv[tid]  = ((float)t - 4.f) * isd;
    }
    __syncthreads();

    unsigned mbit0, mbit1;
    {
        int lane = tid & 31;
        mbit0 = __ballot_sync(0xffffffffu, sm.m0[lane] > 0.f);
        mbit1 = __ballot_sync(0xffffffffu, sm.m0[lane + 32] > 0.f);
    }

    {
        const int r = tid >> 2, c0 = (tid & 3) * 16;
        const int t = sm.tok[r];
        const float isd  = sm.isd[r];
        const float dvv  = sm.dv[r];
        const float isop = (t >= 14 && t <= 17) ? 1.f : 0.f;
        const float opt  = isop * ((float)t - 13.f);
        const float* erow = emb + t * 64;
        const float kfreq2 = (float)(-13.287712379549449 / 64.0);
        #pragma unroll 4
        for (int c = 0; c < 16; c++) {
            int cc = c0 + c;
            float base = erow[cc] * 8.f
                       + dvv  * np_w[cc]       + isd  * np_w[64 + cc]
                       + opt  * np_w[128 + cc] + isop * np_w[192 + cc]
                       + np_b[cc];
            float freq = ex2f((float)(cc & ~1) * kfreq2);
            float ang  = (float)r * freq;
            float pe   = (cc & 1) ? __cosf(ang) : __sinf(ang);
            sm.X[r * LD + cc] = base + pe;
        }
    }
    __syncthreads();

    float* const Kb = sm.KV;
    float* const Vb = sm.KV + 64 * LD;

    #pragma unroll 1
    for (int l = 0; l < 2; l++) {
        // ---- group attention: tridiagonal scores via Z = C·M ----
        layernorm(sm.X, grp_ln_g + l * 64, grp_ln_b + l * 64, sm.A, tid);
        __syncthreads();
        gemm2d_single<64,false,false>(sm.A, LD, g_wpack + CC_GRPM + l*4096,
                                      g_wpack + CC_ZERO, sm.Bf, LD, tid);
        if (tid < 64) {   // pu = c_i·u , pw = c_i·w
            const ulonglong2* cr = (const ulonglong2*)(sm.A + tid * LD);
            const ulonglong2* up = (const ulonglong2*)(g_wpack + CC_U + l*64);
            const ulonglong2* wp = (const ulonglong2*)(g_wpack + CC_W + l*64);
            ull au = 0ull, aw = 0ull;
            #pragma unroll 4
            for (int m = 0; m < 16; m++) {
                ulonglong2 c = cr[m], uu = up[m], ww = wp[m];
                au = ffma2(c.x, uu.x, au); au = ffma2(c.y, uu.y, au);
                aw = ffma2(c.x, ww.x, aw); aw = ffma2(c.y, ww.y, aw);
            }
            float2 pu = unpack2(au), pw = unpack2(aw);
            sm.pmL[tid] = pu.x + pu.y;
            sm.pmR[tid] = pw.x + pw.y;
        }
        __syncthreads();
        if (tid < 63 || (tid >= 64 && tid < 127)) {
            const int up = (tid < 63);
            const int i  = up ? tid : (tid - 64);
            const ulonglong2* zp = (const ulonglong2*)(sm.Bf + (up ? i : i + 1) * LD);
            const ulonglong2* cp = (const ulonglong2*)(sm.A  + (up ? i + 1 : i) * LD);
            ull acc = 0ull;
            #pragma unroll 4
            for (int m = 0; m < 16; m++) {
                ulonglong2 z4 = zp[m], c4 = cp[m];
                acc = ffma2(z4.x, c4.x, acc);
                acc = ffma2(z4.y, c4.y, acc);
            }
            float2 p = unpack2(acc);
            float extra = up ? (sm.pmL[i] + sm.pmR[i + 1])
                             : (sm.pmL[i + 1] + sm.pmR[i]);
            float sv = (p.x + p.y + extra + g_wpack[CC_K0 + l]) * SGRP;
            if (up) sm.s1[i] = sv; else sm.s2[i] = sv;
        }
        __syncthreads();
        // neighbor softmax + symmetrize + prior mix (prior from prev q1 / prev S)
        if (tid < 64) {
            const int i = tid;
            const float m_i = sm.m0[i];
            bool vL = (i > 0)  && m_i > 0.f && sm.m0[i-1] > 0.f;
            bool vR = (i < 63) && m_i > 0.f && sm.m0[i+1] > 0.f;
            float pr_i, ps_i;
            if (!vL && !vR) { pr_i = 1.f/64.f; ps_i = 1.f/64.f; }
            else {
                float sL = vL ? sm.s2[i-1] : -3.4e38f;
                float sR = vR ? sm.s1[i]   : -3.4e38f;
                float m  = fmaxf(sL, sR);
                float eL = vL ? ex2f(sL - m) : 0.f;
                float eR = vR ? ex2f(sR - m) : 0.f;
                pr_i = eR / (eL + eR); ps_i = 0.f;
            }
            float nbd = sqrtf(ps_i * ps_i + 1e-9f);
            if (l > 0) { float pp = sm.q1[i]; nbd = pp + (1.f - pp) * nbd; }   // prev diag
            float q1new = nbd;
            float q2new = 0.f;
            if (i < 63) {
                const int i1 = i + 1;
                bool vL1 = m_i > 0.f && sm.m0[i1] > 0.f;
                bool vR1 = (i1 < 63) && sm.m0[i1] > 0.f && sm.m0[i1+1] > 0.f;
                float pl1;
                if (!vL1 && !vR1) pl1 = 1.f/64.f;
                else {
                    float sL = vL1 ? sm.s2[i]  : -3.4e38f;
                    float sR = vR1 ? sm.s1[i1] : -3.4e38f;
                    float m  = fmaxf(sL, sR);
                    float eL = vL1 ? ex2f(sL - m) : 0.f;
                    float eR = vR1 ? ex2f(sR - m) : 0.f;
                    pl1 = eL / (eL + eR);
                }
                float nbu = sqrtf(pr_i * pl1 + 1e-9f);
                if (l > 0) {   // prev superdiag from prev S
                    float pp = ex2f(sm.S[i1] - sm.S[i]) + 1e-9f;
                    nbu = pp + (1.f - pp) * nbu;
                }
                q2new = lg2f_(nbu + 1e-9f);
            }
            sm.q1[i] = q1new;
            sm.q2[i] = q2new;
        }
        __syncthreads();
        if (tid < 32) {   // exclusive scan of q2 -> S (overwrites prev S)
            float a0 = sm.q2[2*tid], a1 = sm.q2[2*tid+1];
            float p = a0 + a1;
            #pragma unroll
            for (int d = 1; d < 32; d <<= 1) {
                float tshf = __shfl_up_sync(0xffffffffu, p, d);
                if ((int)tid >= d) p += tshf;
            }
            sm.S[2*tid+1] = p - a1;
            if (tid < 31) sm.S[2*tid+2] = p;
            if (tid == 0) sm.S[0] = 0.f;
        }
        __syncthreads();

        // ---- multi-head attention ----
        layernorm(sm.X, ln1_g + l * 64, ln1_b + l * 64, sm.A, tid);
        __syncthreads();
        gemm2d_dual<false>(sm.A, LD, g_wpack + CC_AQK + l*8192,
                           attn_b + (l*4+0)*64, attn_b + (l*4+1)*64, sm.Bf, Kb, LD, tid);
        gemm2d_single<64,false,false>(sm.A, LD, g_wpack + CC_V + l*4096,
                                      attn_b + (l*4+2)*64, Vb, LD, tid);
        __syncthreads();
        // fused attention, g computed inline from S/q1 (no G matrix)
        {
            const int warp = tid >> 5, lane = tid & 31;
            const int h = warp >> 1;
            const int r = (warp & 1) * 32 + lane;
            const ull satt2 = pack2(SATT, SATT);
            const ulonglong2* qp = (const ulonglong2*)(sm.Bf + r * LD + h * 16);
            ulonglong2 qA = qp[0], qB = qp[1], qC = qp[2], qD = qp[3];
            qA.x = mul2(qA.x, satt2); qA.y = mul2(qA.y, satt2);
            qB.x = mul2(qB.x, satt2); qB.y = mul2(qB.y, satt2);
            qC.x = mul2(qC.x, satt2); qC.y = mul2(qC.y, satt2);
            qD.x = mul2(qD.x, satt2); qD.y = mul2(qD.y, satt2);
            const float S_r  = sm.S[r];
            const float q1_r = sm.q1[r];
            ull o[8];
            #pragma unroll
            for (int k = 0; k < 8; k++) o[k] = 0ull;
            float Z = 0.f;
            #pragma unroll 4
            for (int j = 0; j < 64; j++) {
                const ulonglong2* kp = (const ulonglong2*)(Kb + j * LD + h * 16);
                ulonglong2 kA = kp[0], kB = kp[1], kC = kp[2], kD = kp[3];
                ull acc = 0ull;
                acc = ffma2(qA.x, kA.x, acc);
                acc = ffma2(qA.y, kA.y, acc);
                acc = ffma2(qB.x, kB.x, acc);
                acc = ffma2(qB.y, kB.y, acc);
                acc = ffma2(qC.x, kC.x, acc);
                acc = ffma2(qC.y, kC.y, acc);
                acc = ffma2(qD.x, kD.x, acc);
                acc = ffma2(qD.y, kD.y, acc);
                float2 p = unpack2(acc);
                unsigned vbit = (j < 32) ? (mbit0 >> j) : (mbit1 >> (j - 32));
                float e = (vbit & 1u) ? ex2f(p.x + p.y) : 0.f;
                Z += e;
                float Sj = sm.S[j];
                float dd = (j > r) ? (Sj - S_r) : (S_r - Sj);
                float g  = ex2f(dd) + 1e-9f;
                if (j == r) g = q1_r;
                float w = e * g;
                ull wb = pack2(w, w);
                const ulonglong2* vp = (const ulonglong2*)(Vb + j * LD + h * 16);
                ulonglong2 vA = vp[0], vB = vp[1], vC = vp[2], vD = vp[3];
                o[0] = ffma2(wb, vA.x, o[0]); o[1] = ffma2(wb, vA.y, o[1]);
                o[2] = ffma2(wb, vB.x, o[2]); o[3] = ffma2(wb, vB.y, o[3]);
                o[4] = ffma2(wb, vC.x, o[4]); o[5] = ffma2(wb, vC.y, o[5]);
                o[6] = ffma2(wb, vD.x, o[6]); o[7] = ffma2(wb, vD.y, o[7]);
            }
            if (Z == 0.f) {   // all-masked row: uniform 1/64 softmax
                #pragma unroll
                for (int k = 0; k < 8; k++) o[k] = 0ull;
                for (int j = 0; j < 64; j++) {
                    float Sj = sm.S[j];
                    float dd = (j > r) ? (Sj - S_r) : (S_r - Sj);
                    float g  = ex2f(dd) + 1e-9f;
                    if (j == r) g = q1_r;
                    float w = g * 0.015625f;
                    ull wb = pack2(w, w);
                    const ulonglong2* vp = (const ulonglong2*)(Vb + j * LD + h * 16);
                    ulonglong2 vA = vp[0], vB = vp[1], vC = vp[2], vD = vp[3];
                    o[0] = ffma2(wb, vA.x, o[0]); o[1] = ffma2(wb, vA.y, o[1]);
                    o[2] = ffma2(wb, vB.x, o[2]); o[3] = ffma2(wb, vB.y, o[3]);
                    o[4] = ffma2(wb, vC.x, o[4]); o[5] = ffma2(wb, vC.y, o[5]);
                    o[6] = ffma2(wb, vD.x, o[6]); o[7] = ffma2(wb, vD.y, o[7]);
                }
                Z = 1.f;
            }
            const float invZ = 1.f / Z;
            const ull zb = pack2(invZ, invZ);
            float* op = sm.Bf + r * LD + h * 16;
            #pragma unroll
            for (int k = 0; k < 4; k++) {
                float2 pa = unpack2(mul2(o[2*k],   zb));
                float2 pb = unpack2(mul2(o[2*k+1], zb));
                float4 st; st.x = pa.x; st.y = pa.y; st.z = pb.x; st.w = pb.y;
                *(float4*)(op + 4*k) = st;
            }
        }
        __syncthreads();
        gemm2d_single<64,false,true>(sm.Bf, LD, g_wpack + CC_O + l*4096,
                                     attn_b + (l*4+3)*64, sm.X, LD, tid);
        __syncthreads();

        // ---- FFN ----
        layernorm(sm.X, ln2_g + l * 64, ln2_b + l * 64, sm.A, tid);
        __syncthreads();
        gemm2d_dual<true>(sm.A, LD, ffn_w1 + l*8192,
                          ffn_b1 + l*128, ffn_b1 + l*128 + 64, sm.KV, sm.KV + 64, LDF, tid);
        __syncthreads();
        gemm2d_single<128,false,true>(sm.KV, LDF, g_wpack + CC_FFN2 + l*8192,
                                      ffn_b2 + l*64, sm.X, LD, tid);
        __syncthreads();
    }

    // ================= readout =================
    layernorm(sm.X, enc_g, enc_b, sm.A, tid);
    __syncthreads();
    if (tid < 64) {
        const ulonglong2* xr = (const ulonglong2*)(sm.A + tid * LD);
        const ulonglong2* wr = (const ulonglong2*)red_w;
        ull acc = 0ull;
        #pragma unroll 4
        for (int m = 0; m < 16; m++) {
            ulonglong2 x4 = xr[m], w4 = wr[m];
            acc = ffma2(x4.x, w4.x, acc);
            acc = ffma2(x4.y, w4.y, acc);
        }
        float2 p = unpack2(acc);
        float s = p.x + p.y + red_b[0];
        s += (1.f - sm.m0[tid]) * (-1e9f);
        sm.s1[tid] = s;
    }
    __syncthreads();
    if (tid < 32) {
        float m = fmaxf(sm.s1[tid], sm.s1[tid + 32]);
        #pragma unroll
        for (int d = 16; d >= 1; d >>= 1) m = fmaxf(m, __shfl_xor_sync(0xffffffffu, m, d));
        if (tid == 0) sm.scal[0] = m;
    }
    __syncthreads();
    if (tid < 64) sm.s2[tid] = ex2f((sm.s1[tid] - sm.scal[0]) * LOG2E);
    __syncthreads();
    if (tid < 32) {
        float z = sm.s2[tid] + sm.s2[tid + 32];
        #pragma unroll
        for (int d = 16; d >= 1; d >>= 1) z += __shfl_xor_sync(0xffffffffu, z, d);
        if (tid == 0) sm.scal[1] = z;
    }
    __syncthreads();
    if (tid < 64) sm.rw[tid] = sm.s2[tid] / sm.scal[1];
    __syncthreads();
    if (tid < 32) {
        float a0 = sm.rw[2*tid], a1 = sm.rw[2*tid+1];
        float p = a0 + a1;
        #pragma unroll
        for (int d = 1; d < 32; d <<= 1) {
            float tshf = __shfl_up_sync(0xffffffffu, p, d);
            if ((int)tid >= d) p += tshf;
        }
        sm.cum[2*tid+1] = p;
        sm.cum[2*tid]   = p - a1;
    }
    __syncthreads();
    if (tid < 64) {
        sm.pmL[tid] = (1.f - sm.cum[tid]) * sm.isd[tid];
        sm.pmR[tid] = (sm.cum[tid] - sm.rw[tid]) * sm.isd[tid];
    }
    if (tid >= 64 && tid < 128) {
        int h = tid - 64;
        float p = 0.f;
        #pragma unroll 8
        for (int ll = 0; ll < 64; ll++) p = fmaf(sm.A[ll * LD + h], sm.rw[ll], p);
        sm.pooled[h] = p;
    }
    __syncthreads();
    if (tid < 64) {
        const int lane = tid & 31;
        const float* pm = (tid < 32) ? sm.pmL : sm.pmR;
        float a0 = pm[2*lane], a1 = pm[2*lane+1];
        float p = a0 + a1;
        #pragma unroll
        for (int d = 1; d < 32; d <<= 1) {
            float tshf = __shfl_up_sync(0xffffffffu, p, d);
            if (lane >= d) p += tshf;
        }
        float tot  = __shfl_sync(0xffffffffu, p, 31);
        float run1 = p, run0 = p - a1;
        float d0 = sm.dv[2*lane], d1 = sm.dv[2*lane+1];
        float acc = d0 * ex2f((tot - run0) * a0 * LOG2_10) * a0
                  + d1 * ex2f((tot - run1) * a1 * LOG2_10) * a1;
        #pragma unroll
        for (int d = 16; d >= 1; d >>= 1) acc += __shfl_xor_sync(0xffffffffu, acc, d);
        if (lane == 0) sm.scal[(tid < 32) ? 5 : 6] = acc;
    } else if (tid >= 64 && tid < 96) {
        const int lane = tid & 31;
        float p0 = sm.pooled[lane], p1 = sm.pooled[lane + 32];
        float l0 = p0 * opc_w[lane*4+0] + p1 * opc_w[(lane+32)*4+0];
        float l1 = p0 * opc_w[lane*4+1] + p1 * opc_w[(lane+32)*4+1];
        float l2 = p0 * opc_w[lane*4+2] + p1 * opc_w[(lane+32)*4+2];
        float l3 = p0 * opc_w[lane*4+3] + p1 * opc_w[(lane+32)*4+3];
        #pragma unroll
        for (int d = 16; d >= 1; d >>= 1) {
            l0 += __shfl_xor_sync(0xffffffffu, l0, d);
            l1 += __shfl_xor_sync(0xffffffffu, l1, d);
            l2 += __shfl_xor_sync(0xffffffffu, l2, d);
            l3 += __shfl_xor_sync(0xffffffffu, l3, d);
        }
        if (lane == 0) {
            sm.s1[0] = l0 + opc_b[0];
            sm.s1[1] = l1 + opc_b[1];
            sm.s1[2] = l2 + opc_b[2];
            sm.s1[3] = l3 + opc_b[3];
        }
    }
    __syncthreads();
    if (tid == 0) {
        float lv = sm.scal[5], rv = sm.scal[6];
        float lg0 = sm.s1[0], lg1 = sm.s1[1], lg2 = sm.s1[2], lg3 = sm.s1[3];
        int op = 0; float bm = lg0;
        if (lg1 > bm) { bm = lg1; op = 1; }
        if (lg2 > bm) { bm = lg2; op = 2; }
        if (lg3 > bm) { bm = lg3; op = 3; }
        float result, valid = 1.f;
        if      (op == 0) result = lv + rv;
        else if (op == 1) result = lv - rv;
        else if (op == 2) result = lv * rv;
        else {
            bool bad = fabsf(rv) < 1e-6f;
            result = bad ? 0.f : lv / rv;
            valid  = bad ? 0.f : 1.f;
        }
        float sgn = (result > 0.f) ? 1.f : ((result < 0.f) ? -1.f : 0.f);
        float rc  = sgn * log1pf(fabsf(result));
        sm.scal[2] = result; sm.scal[3] = valid; sm.scal[4] = rc;
    }
    __syncthreads();

    const bool full = (out_size >= 136 * NB);
    if (full) {
        if (tid == 0) {
            out[b]           = sm.scal[2];
            out[65*NB + b]   = sm.scal[3];
            out[66*NB + b]   = sm.scal[5];
            out[67*NB + b]   = sm.scal[6];
            #pragma unroll
            for (int o = 0; o < 4; o++) out[68*NB + b*4 + o] = sm.s1[o];
        }
        if (tid < 64) {
            float rc = sm.scal[4], valid = sm.scal[3];
            out[NB + b*64 + tid]    = rc * res_w[tid] + valid * res_w[64 + tid] + res_b[tid];
            out[72*NB + b*64 + tid] = sm.rw[tid];
        }
    } else {
        if (tid == 0) out[b] = sm.scal[2];
    }
}

extern "C" void kernel_launch(void* const* d_in, const int* in_sizes, int n_in,
                              void* d_out, int out_size)
{
    pack_weights<<<(WP_TOTAL + 255) / 256, 256>>>(
        (const float*)d_in[4],   // grp_wq
        (const float*)d_in[6],   // grp_wk
        (const float*)d_in[5],   // grp_bq
        (const float*)d_in[7],   // grp_bk
        (const float*)d_in[10],  // attn_w
        (const float*)d_in[18]); // ffn_w2

    const size_t shmem = sizeof(Smem);
    cudaFuncSetAttribute(fsa_kernel, cudaFuncAttributeMaxDynamicSharedMemorySize, (int)shmem);
    fsa_kernel<<<NB, 256, shmem>>>(
        (const int*)  d_in[0],
        (const float*)d_in[1],
        (const float*)d_in[2],  (const float*)d_in[3],    // np_w, np_b
        (const float*)d_in[8],  (const float*)d_in[9],    // grp_ln_g, grp_ln_b
        (const float*)d_in[11],                            // attn_b
        (const float*)d_in[12], (const float*)d_in[13],   // ln1_g, ln1_b
        (const float*)d_in[14], (const float*)d_in[15],   // ln2_g, ln2_b
        (const float*)d_in[16],                            // ffn_w1
        (const float*)d_in[17], (const float*)d_in[19],   // ffn_b1, ffn_b2
        (const float*)d_in[20], (const float*)d_in[21],   // enc_g, enc_b
        (const float*)d_in[22], (const float*)d_in[23],   // red_w, red_b
        (const float*)d_in[24], (const float*)d_in[25],   // opc_w, opc_b
        (const float*)d_in[26], (const float*)d_in[27],   // res_w, res_b
        (float*)d_out, out_size);
}